// round 13
// baseline (speedup 1.0000x reference)
#include <cuda_runtime.h>
#include <cuda_fp16.h>
#include <math.h>
#include <stdint.h>

#define T_TOK 4096
#define DIM   2048
#define NEXP  16
#define FDIM  768
#define NSLOT (T_TOK * 2)
#define MTILES 64
#define WSZ ((size_t)NEXP * FDIM * DIM)

// ---------------- device scratch; NEVER passed as kernel args (ATS host-shadow hazard) ----------------
__device__ __align__(16) int      g_off[NEXP + 1];
__device__ __align__(16) int      g_tok_e[NSLOT];
__device__ __align__(16) float    g_tok_w[NSLOT];
__device__ __align__(16) int      g_perm[NSLOT];
__device__ __align__(16) float    g_wt[NSLOT];
__device__ __align__(16) uint32_t g_Wh[3 * WSZ / 2];              // fp16x2: [gate|up|down]
__device__ __align__(16) uint32_t g_Xh[(size_t)T_TOK * DIM / 2];  // x fp16
__device__ __align__(16) uint32_t g_Hh[(size_t)NSLOT * FDIM / 2]; // h fp16

// ---------------- helpers ----------------
__device__ __forceinline__ uint32_t smem_u32(const void* p) {
    uint32_t a;
    asm("{ .reg .u64 t; cvta.to.shared.u64 t, %1; cvt.u32.u64 %0, t; }" : "=r"(a) : "l"(p));
    return a;
}
#define CP16(dst, src, sz) \
    asm volatile("cp.async.cg.shared.global [%0], [%1], 16, %2;" \
        :: "r"(dst), "l"(src), "r"(sz) : "memory")
#define CP_COMMIT() asm volatile("cp.async.commit_group;" ::: "memory")
#define CP_WAIT1()  asm volatile("cp.async.wait_group 1;" ::: "memory")
#define CP_WAIT0()  asm volatile("cp.async.wait_group 0;" ::: "memory")

__device__ __forceinline__ void ldm4(uint32_t* r, uint32_t addr) {
    asm volatile("ldmatrix.sync.aligned.m8n8.x4.shared.b16 {%0,%1,%2,%3}, [%4];"
        : "=r"(r[0]), "=r"(r[1]), "=r"(r[2]), "=r"(r[3]) : "r"(addr));
}
__device__ __forceinline__ void mma16816(float* d, const uint32_t* a, uint32_t b0, uint32_t b1) {
    asm volatile(
        "mma.sync.aligned.m16n8k16.row.col.f32.f16.f16.f32 "
        "{%0,%1,%2,%3}, {%4,%5,%6,%7}, {%8,%9}, {%0,%1,%2,%3};"
        : "+f"(d[0]), "+f"(d[1]), "+f"(d[2]), "+f"(d[3])
        : "r"(a[0]), "r"(a[1]), "r"(a[2]), "r"(a[3]), "r"(b0), "r"(b1));
}

// ---------------- zero output ----------------
__global__ void zero_out_kernel(float* __restrict__ out) {
    const size_t i = (size_t)blockIdx.x * blockDim.x + threadIdx.x;
    if (i < (size_t)T_TOK * DIM / 4)
        ((float4*)out)[i] = make_float4(0.f, 0.f, 0.f, 0.f);
}

// ---------------- all-weights fp32 -> fp16 in ONE launch (grid.y = slice) ----------------
__global__ void conv_all_kernel(const float4* __restrict__ gw,
                                const float4* __restrict__ uw,
                                const float4* __restrict__ dw) {
    const int slice = blockIdx.y;
    const float4* src = (slice == 0) ? gw : (slice == 1) ? uw : dw;
    const size_t base = (size_t)slice * (WSZ / 2);
    const size_t n4 = WSZ / 4;
    for (size_t i = (size_t)blockIdx.x * blockDim.x + threadIdx.x; i < n4;
         i += (size_t)gridDim.x * blockDim.x) {
        const float4 v = src[i];
        __half2 h0 = __floats2half2_rn(v.x, v.y);
        __half2 h1 = __floats2half2_rn(v.z, v.w);
        uint2 u;
        u.x = *(uint32_t*)&h0; u.y = *(uint32_t*)&h1;
        *(uint2*)&g_Wh[base + 2 * i] = u;
    }
}

// ---------------- router (proven) + fused x->fp16 conversion ----------------
__global__ __launch_bounds__(256)
void router_kernel(const float* __restrict__ x,
                   const float* __restrict__ rw,
                   float* __restrict__ logits_out,
                   int write_logits) {
    __shared__ float xs[DIM];
    __shared__ float lg[NEXP];
    const int t = blockIdx.x;
    const int tid = threadIdx.x;
    const int warp = tid >> 5, lane = tid & 31;

    const float4* xg = (const float4*)(x + (size_t)t * DIM);
    for (int i = tid; i < DIM / 4; i += 256) ((float4*)xs)[i] = xg[i];
    __syncthreads();

    // fused: emit fp16 copy of this token row (replaces xhalf_kernel)
    for (int i = tid; i < DIM / 4; i += 256) {
        const float4 v = ((const float4*)xs)[i];
        __half2 h0 = __floats2half2_rn(v.x, v.y);
        __half2 h1 = __floats2half2_rn(v.z, v.w);
        uint2 u;
        u.x = *(uint32_t*)&h0; u.y = *(uint32_t*)&h1;
        *(uint2*)&g_Xh[(size_t)t * (DIM / 2) + 2 * i] = u;
    }

    {
        const float4* w0 = (const float4*)(rw + (size_t)(warp * 2) * DIM);
        const float4* w1 = (const float4*)(rw + (size_t)(warp * 2 + 1) * DIM);
        float a0 = 0.f, a1 = 0.f;
        for (int i = lane; i < DIM / 4; i += 32) {
            const float4 xv = ((const float4*)xs)[i];
            const float4 va = w0[i];
            const float4 vb = w1[i];
            a0 += xv.x * va.x + xv.y * va.y + xv.z * va.z + xv.w * va.w;
            a1 += xv.x * vb.x + xv.y * vb.y + xv.z * vb.z + xv.w * vb.w;
        }
        #pragma unroll
        for (int o = 16; o > 0; o >>= 1) {
            a0 += __shfl_xor_sync(0xffffffffu, a0, o);
            a1 += __shfl_xor_sync(0xffffffffu, a1, o);
        }
        if (lane == 0) { lg[warp * 2] = a0; lg[warp * 2 + 1] = a1; }
    }
    __syncthreads();
    if (write_logits && tid < NEXP)
        logits_out[(size_t)t * NEXP + tid] = lg[tid];
    if (tid == 0) {
        int i0 = 0;
        #pragma unroll
        for (int i = 1; i < NEXP; i++)
            if (lg[i] > lg[i0]) i0 = i;
        int i1 = (i0 == 0) ? 1 : 0;
        #pragma unroll
        for (int i = 0; i < NEXP; i++) {
            if (i == i0) continue;
            if (lg[i] > lg[i1]) i1 = i;
        }
        const float e1 = __expf(lg[i1] - lg[i0]);
        const float s = 1.0f + e1;
        g_tok_e[2 * t + 0] = i0; g_tok_w[2 * t + 0] = 1.0f / s;
        g_tok_e[2 * t + 1] = i1; g_tok_w[2 * t + 1] = e1 / s;
    }
}

// ---------------- compaction (proven) ----------------
__global__ void route_build_kernel() {
    __shared__ int s_cnt[NEXP];
    __shared__ int s_off[NEXP + 1];
    const int tid = threadIdx.x;
    if (tid < NEXP) s_cnt[tid] = 0;
    __syncthreads();
    for (int i = tid; i < NSLOT; i += 512)
        atomicAdd(&s_cnt[g_tok_e[i] & (NEXP - 1)], 1);
    __syncthreads();
    if (tid == 0) {
        int off = 0;
        #pragma unroll
        for (int e = 0; e < NEXP; e++) { s_off[e] = off; g_off[e] = off; off += s_cnt[e]; }
        s_off[NEXP] = off; g_off[NEXP] = off;
    }
    __syncthreads();
    const int warp = tid >> 5, lane = tid & 31;
    int base = s_off[warp];
    for (int i0 = 0; i0 < NSLOT; i0 += 32) {
        const int i = i0 + lane;
        const bool m = ((g_tok_e[i] & (NEXP - 1)) == warp);
        const unsigned mask = __ballot_sync(0xffffffffu, m);
        if (m) {
            const int pos = base + __popc(mask & ((1u << lane) - 1u));
            if (pos < NSLOT) {
                g_perm[pos] = i >> 1;
                g_wt[pos]   = g_tok_w[i];
            }
        }
        base += __popc(mask);
    }
}

// ================= fused gate+up fp16 GEMM with in-register SwiGLU epilogue =================
// Tile M=128 x N=64 for BOTH gate and up. K=2048, chunk 32, 3-stage cp.async,
// single barrier per chunk, issue-early.
// Stage 20480 B: A 0..10240 | Bg 10240..15360 | Bu 15360..20480 (80 B row stride).
#define GU_SMEM (3 * 20480)
__global__ __launch_bounds__(256, 2)
void gu_kernel() {
    constexpr int NC = DIM / 32;
    extern __shared__ char smem[];
    __shared__ int   s_rows[128];
    __shared__ float s_w[128];

    const int tid = threadIdx.x;
    const int lane = tid & 31, wid = tid >> 5;
    const int wm = wid >> 1, wn = wid & 1;          // 4 x 2 warps; warp tile 32 x 32 per matrix

    const int e  = blockIdx.y / MTILES;
    const int mt = blockIdx.y % MTILES;
    int segBeg = g_off[e], segEnd = g_off[e + 1];
    if (segBeg < 0) segBeg = 0;
    if (segEnd > NSLOT) segEnd = NSLOT;
    const int m0 = segBeg + mt * 128;
    if (m0 >= segEnd) return;
    const int mrem = segEnd - m0;
    const int n0 = blockIdx.x * 64;

    if (tid < 128) {
        const int idx = m0 + tid;
        int r = -1; float w = 0.f;
        if (idx < segEnd) {
            r = g_perm[idx];
            if (r < 0) r = 0;
            if (r >= T_TOK) r = T_TOK - 1;
            w = g_wt[idx];
        }
        s_rows[tid] = r; s_w[tid] = w;
    }
    __syncthreads();

    const uint32_t sb = smem_u32(smem);
    const int arow = tid >> 1, acg = tid & 1;

    auto ISSUE = [&](int c) {
        const uint32_t st = sb + (uint32_t)(c % 3) * 20480u;
        const int k0 = c * 32;
        {   // A: gathered x fp16
            const int r = s_rows[arow];
            const uint32_t sz = (r >= 0) ? 16u : 0u;
            const size_t ao = (((size_t)(r < 0 ? 0 : r) * DIM + k0) >> 1) + (size_t)acg * 8;
            const uint32_t da = st + (uint32_t)(arow * 80 + acg * 32);
            const uint64_t sa = __cvta_generic_to_global((const void*)(g_Xh + ao));
            CP16(da,      sa,      sz);
            CP16(da + 16, sa + 16, sz);
        }
        {   // B: gate rows 0-63, up rows 64-127
            const int gu = arow >> 6;
            const int row = arow & 63;
            const size_t bo = (size_t)gu * (WSZ / 2)
                            + ((((size_t)e * FDIM + n0 + row) * DIM + k0) >> 1) + (size_t)acg * 8;
            const uint32_t db = st + 10240u + (uint32_t)(gu * 5120 + row * 80 + acg * 32);
            const uint64_t sb2 = __cvta_generic_to_global((const void*)(g_Wh + bo));
            CP16(db,      sb2,      16u);
            CP16(db + 16, sb2 + 16, 16u);
        }
        CP_COMMIT();
    };

    float acc[2][2][4][4];   // [gu][mi][n-frag][4]
    #pragma unroll
    for (int a = 0; a < 2; a++)
        #pragma unroll
        for (int b = 0; b < 2; b++)
            #pragma unroll
            for (int cN = 0; cN < 4; cN++)
                #pragma unroll
                for (int d = 0; d < 4; d++) acc[a][b][cN][d] = 0.f;

    const int lr = lane & 15, lh = lane >> 4;

    ISSUE(0); ISSUE(1);
    for (int c = 0; c < NC; c++) {
        if (c + 1 < NC) { CP_WAIT1(); } else { CP_WAIT0(); }
        __syncthreads();                 // single barrier per chunk (3-stage ring is write-safe)
        if (c + 2 < NC) ISSUE(c + 2);    // issue-early: loads fly during MMA below
        const uint32_t st = sb + (uint32_t)(c % 3) * 20480u;
        #pragma unroll
        for (int ks = 0; ks < 2; ks++) {
            uint32_t ah[2][4], bh[2][2][4];
            #pragma unroll
            for (int mi = 0; mi < 2; mi++)
                ldm4(ah[mi], st + (uint32_t)((wm * 32 + mi * 16 + lr) * 80 + ks * 32 + lh * 16));
            #pragma unroll
            for (int gu = 0; gu < 2; gu++)
                #pragma unroll
                for (int ni = 0; ni < 2; ni++)
                    ldm4(bh[gu][ni], st + 10240u + (uint32_t)(gu * 5120
                        + (wn * 32 + ni * 16 + lr) * 80 + ks * 32 + lh * 16));
            #pragma unroll
            for (int gu = 0; gu < 2; gu++)
                #pragma unroll
                for (int mi = 0; mi < 2; mi++)
                    #pragma unroll
                    for (int ni = 0; ni < 2; ni++)
                        #pragma unroll
                        for (int j = 0; j < 2; j++)
                            mma16816(acc[gu][mi][ni * 2 + j], ah[mi], bh[gu][ni][j], bh[gu][ni][j + 2]);
        }
    }

    // ---- epilogue: h = wt * silu(g) * u -> fp16 -> g_Hh ----
    const int t4 = lane >> 2, l3 = lane & 3;
    #pragma unroll
    for (int mi = 0; mi < 2; mi++) {
        #pragma unroll
        for (int half = 0; half < 2; half++) {
            const int row = wm * 32 + mi * 16 + t4 + half * 8;
            if (row < mrem) {
                const float wt = s_w[row];
                const size_t base = (size_t)(m0 + row) * (FDIM / 2) + (size_t)((n0 + wn * 32) >> 1) + l3;
                #pragma unroll
                for (int nj = 0; nj < 4; nj++) {
                    const float gx = acc[0][mi][nj][half * 2 + 0];
                    const float gy = acc[0][mi][nj][half * 2 + 1];
                    const float ux = acc[1][mi][nj][half * 2 + 0];
                    const float uy = acc[1][mi][nj][half * 2 + 1];
                    const float hx = wt * ux * (gx / (1.f + __expf(-gx)));
                    const float hy = wt * uy * (gy / (1.f + __expf(-gy)));
                    __half2 hh = __floats2half2_rn(hx, hy);
                    g_Hh[base + nj * 4] = *(uint32_t*)&hh;
                }
            }
        }
    }
}

// ================= down fp16 GEMM (3-stage, single-barrier, scatter-add epilogue) =================
// Tile M=128 x N=128. K=768, chunk 32. Stage 20480 B: A 0..10240 | B 10240..20480.
#define DN_SMEM (3 * 20480)
__global__ __launch_bounds__(256, 2)
void dn_kernel(float* __restrict__ out) {
    constexpr int NC = FDIM / 32;
    extern __shared__ char smem[];

    const int tid = threadIdx.x;
    const int lane = tid & 31, wid = tid >> 5;
    const int wm = wid >> 2, wn = wid & 3;

    const int e  = blockIdx.y / MTILES;
    const int mt = blockIdx.y % MTILES;
    int segBeg = g_off[e], segEnd = g_off[e + 1];
    if (segBeg < 0) segBeg = 0;
    if (segEnd > NSLOT) segEnd = NSLOT;
    const int m0 = segBeg + mt * 128;
    if (m0 >= segEnd) return;
    const int mrem = segEnd - m0;
    const int n0 = blockIdx.x * 128;

    const uint32_t sb = smem_u32(smem);
    const int arow = tid >> 1, acg = tid & 1;

    auto ISSUE = [&](int c) {
        const uint32_t st = sb + (uint32_t)(c % 3) * 20480u;
        const int k0 = c * 32;
        {   // A: h fp16, slot-indexed
            const uint32_t sz = (arow < mrem) ? 16u : 0u;
            const int r = m0 + ((arow < mrem) ? arow : 0);
            const size_t ao = (((size_t)r * FDIM + k0) >> 1) + (size_t)acg * 8;
            const uint32_t da = st + (uint32_t)(arow * 80 + acg * 32);
            const uint64_t sa = __cvta_generic_to_global((const void*)(g_Hh + ao));
            CP16(da,      sa,      sz);
            CP16(da + 16, sa + 16, sz);
        }
        {   // B: down weights (slice 2 at uint32 offset WSZ)
            const size_t bo = WSZ + ((((size_t)e * DIM + n0 + arow) * FDIM + k0) >> 1) + (size_t)acg * 8;
            const uint32_t db = st + 10240u + (uint32_t)(arow * 80 + acg * 32);
            const uint64_t sb2 = __cvta_generic_to_global((const void*)(g_Wh + bo));
            CP16(db,      sb2,      16u);
            CP16(db + 16, sb2 + 16, 16u);
        }
        CP_COMMIT();
    };

    float acc[4][4][4];
    #pragma unroll
    for (int i = 0; i < 4; i++)
        #pragma unroll
        for (int j = 0; j < 4; j++)
            #pragma unroll
            for (int k = 0; k < 4; k++) acc[i][j][k] = 0.f;

    const int lr = lane & 15, lh = lane >> 4;
    const uint32_t aoffw = (uint32_t)((wm * 64 + lr) * 80 + lh * 16);
    const uint32_t boffw = (uint32_t)(10240 + (wn * 32 + lr) * 80 + lh * 16);

    ISSUE(0); ISSUE(1);
    for (int c = 0; c < NC; c++) {
        if (c + 1 < NC) { CP_WAIT1(); } else { CP_WAIT0(); }
        __syncthreads();                 // single barrier per chunk
        if (c + 2 < NC) ISSUE(c + 2);    // issue-early
        const uint32_t st = sb + (uint32_t)(c % 3) * 20480u;
        #pragma unroll
        for (int ks = 0; ks < 2; ks++) {
            uint32_t ah[4][4], bh[2][4];
            #pragma unroll
            for (int mi = 0; mi < 4; mi++)
                ldm4(ah[mi], st + aoffw + mi * 16 * 80 + ks * 32);
            #pragma unroll
            for (int ni = 0; ni < 2; ni++)
                ldm4(bh[ni], st + boffw + ni * 16 * 80 + ks * 32);
            #pragma unroll
            for (int mi = 0; mi < 4; mi++)
                #pragma unroll
                for (int ni = 0; ni < 2; ni++)
                    #pragma unroll
                    for (int j = 0; j < 2; j++)
                        mma16816(acc[mi][ni * 2 + j], ah[mi], bh[ni][j], bh[ni][j + 2]);
        }
    }

    // ---- epilogue: scatter-add (proven mapping) ----
    const int t4 = lane >> 2, t2 = (lane & 3) * 2;
    #pragma unroll
    for (int mi = 0; mi < 4; mi++) {
        #pragma unroll
        for (int half = 0; half < 2; half++) {
            const int row = wm * 64 + mi * 16 + t4 + half * 8;
            if (row < mrem) {
                int tok = g_perm[m0 + row];
                if (tok < 0) tok = 0;
                if (tok >= T_TOK) tok = T_TOK - 1;
                float* orow = out + (size_t)tok * DIM + n0 + wn * 32;
                #pragma unroll
                for (int nj = 0; nj < 4; nj++) {
                    atomicAdd(orow + nj * 8 + t2,     acc[mi][nj][half * 2 + 0]);
                    atomicAdd(orow + nj * 8 + t2 + 1, acc[mi][nj][half * 2 + 1]);
                }
            }
        }
    }
}

// ---------------- launch ----------------
extern "C" void kernel_launch(void* const* d_in, const int* in_sizes, int n_in,
                              void* d_out, int out_size) {
    long long smax = -1;
    for (int i = 0; i < n_in; i++)
        if ((long long)in_sizes[i] > smax) smax = in_sizes[i];
    const float* w3[3] = {0, 0, 0};
    int wpos[3] = {-1, -1, -1};
    int nw = 0, ih = -1, irt = -1;
    for (int i = 0; i < n_in; i++)
        if ((long long)in_sizes[i] == smax && nw < 3) { w3[nw] = (const float*)d_in[i]; wpos[nw] = i; nw++; }
    long long best_h = -1;
    for (int i = 0; i < n_in; i++) {
        if (i == wpos[0] || i == wpos[1] || i == wpos[2]) continue;
        if ((long long)in_sizes[i] > best_h) { best_h = in_sizes[i]; ih = i; }
    }
    long long best_r = (long long)1 << 62;
    for (int i = 0; i < n_in; i++) {
        if (i == wpos[0] || i == wpos[1] || i == wpos[2] || i == ih) continue;
        if ((long long)in_sizes[i] < best_r) { best_r = in_sizes[i]; irt = i; }
    }
    const float* x  = (ih  >= 0) ? (const float*)d_in[ih]  : (const float*)d_in[0];
    const float* rw = (irt >= 0) ? (const float*)d_in[irt] : (const float*)d_in[1];
    const float *gw, *uw, *dw;
    if (nw == 3) {
        if (ih == 2) { dw = w3[0]; gw = w3[1]; uw = w3[2]; }
        else         { gw = w3[0]; uw = w3[1]; dw = w3[2]; }
    } else {
        x  = (const float*)d_in[0]; rw = (const float*)d_in[1];
        gw = (const float*)d_in[2]; uw = (const float*)d_in[3]; dw = (const float*)d_in[4];
    }
    float* out = (float*)d_out;

    const int need = T_TOK * DIM + T_TOK * NEXP;
    const int write_logits = (out_size >= need) ? 1 : 0;
    float* logits = out + (size_t)T_TOK * DIM;

    cudaFuncSetAttribute(gu_kernel, cudaFuncAttributeMaxDynamicSharedMemorySize, GU_SMEM);
    cudaFuncSetAttribute(dn_kernel, cudaFuncAttributeMaxDynamicSharedMemorySize, DN_SMEM);

    zero_out_kernel<<<(T_TOK * DIM / 4 + 255) / 256, 256>>>(out);
    conv_all_kernel<<<dim3(4096, 3), 256>>>((const float4*)gw, (const float4*)uw, (const float4*)dw);
    router_kernel<<<T_TOK, 256>>>(x, rw, logits, write_logits);
    route_build_kernel<<<1, 512>>>();

    gu_kernel<<<dim3(FDIM / 64, NEXP * MTILES), 256, GU_SMEM>>>();
    dn_kernel<<<dim3(DIM / 128, NEXP * MTILES), 256, DN_SMEM>>>(out);
}

// round 14
// speedup vs baseline: 1.0941x; 1.0941x over previous
#include <cuda_runtime.h>
#include <cuda_fp16.h>
#include <math.h>
#include <stdint.h>

#define T_TOK 4096
#define DIM   2048
#define NEXP  16
#define FDIM  768
#define NSLOT (T_TOK * 2)
#define MTILES 64
#define WSZ ((size_t)NEXP * FDIM * DIM)

// ---------------- device scratch; NEVER passed as kernel args (ATS host-shadow hazard) ----------------
__device__ __align__(16) int      g_off[NEXP + 1];
__device__ __align__(16) int      g_tok_e[NSLOT];
__device__ __align__(16) float    g_tok_w[NSLOT];
__device__ __align__(16) int      g_perm[NSLOT];
__device__ __align__(16) float    g_wt[NSLOT];
__device__ __align__(16) uint32_t g_Wh[3 * WSZ / 2];              // fp16x2: [gate|up|down]
__device__ __align__(16) uint32_t g_Xh[(size_t)T_TOK * DIM / 2];  // x fp16
__device__ __align__(16) uint32_t g_Hh[(size_t)NSLOT * FDIM / 2]; // h fp16

// ---------------- helpers ----------------
__device__ __forceinline__ uint32_t smem_u32(const void* p) {
    uint32_t a;
    asm("{ .reg .u64 t; cvta.to.shared.u64 t, %1; cvt.u32.u64 %0, t; }" : "=r"(a) : "l"(p));
    return a;
}
#define CP16(dst, src, sz) \
    asm volatile("cp.async.cg.shared.global [%0], [%1], 16, %2;" \
        :: "r"(dst), "l"(src), "r"(sz) : "memory")
#define CP_COMMIT() asm volatile("cp.async.commit_group;" ::: "memory")
#define CP_WAIT1()  asm volatile("cp.async.wait_group 1;" ::: "memory")
#define CP_WAIT0()  asm volatile("cp.async.wait_group 0;" ::: "memory")

__device__ __forceinline__ void ldm4(uint32_t* r, uint32_t addr) {
    asm volatile("ldmatrix.sync.aligned.m8n8.x4.shared.b16 {%0,%1,%2,%3}, [%4];"
        : "=r"(r[0]), "=r"(r[1]), "=r"(r[2]), "=r"(r[3]) : "r"(addr));
}
__device__ __forceinline__ void mma16816(float* d, const uint32_t* a, uint32_t b0, uint32_t b1) {
    asm volatile(
        "mma.sync.aligned.m16n8k16.row.col.f32.f16.f16.f32 "
        "{%0,%1,%2,%3}, {%4,%5,%6,%7}, {%8,%9}, {%0,%1,%2,%3};"
        : "+f"(d[0]), "+f"(d[1]), "+f"(d[2]), "+f"(d[3])
        : "r"(a[0]), "r"(a[1]), "r"(a[2]), "r"(a[3]), "r"(b0), "r"(b1));
}

// ---------------- zero output ----------------
__global__ void zero_out_kernel(float* __restrict__ out) {
    const size_t i = (size_t)blockIdx.x * blockDim.x + threadIdx.x;
    if (i < (size_t)T_TOK * DIM / 4)
        ((float4*)out)[i] = make_float4(0.f, 0.f, 0.f, 0.f);
}

// ---------------- all-weights fp32 -> fp16 in ONE launch (grid.y = slice) ----------------
__global__ void conv_all_kernel(const float4* __restrict__ gw,
                                const float4* __restrict__ uw,
                                const float4* __restrict__ dw) {
    const int slice = blockIdx.y;
    const float4* src = (slice == 0) ? gw : (slice == 1) ? uw : dw;
    const size_t base = (size_t)slice * (WSZ / 2);
    const size_t n4 = WSZ / 4;
    for (size_t i = (size_t)blockIdx.x * blockDim.x + threadIdx.x; i < n4;
         i += (size_t)gridDim.x * blockDim.x) {
        const float4 v = src[i];
        __half2 h0 = __floats2half2_rn(v.x, v.y);
        __half2 h1 = __floats2half2_rn(v.z, v.w);
        uint2 u;
        u.x = *(uint32_t*)&h0; u.y = *(uint32_t*)&h1;
        *(uint2*)&g_Wh[base + 2 * i] = u;
    }
}

// ---------------- router (proven) + fused x->fp16 conversion ----------------
__global__ __launch_bounds__(256)
void router_kernel(const float* __restrict__ x,
                   const float* __restrict__ rw,
                   float* __restrict__ logits_out,
                   int write_logits) {
    __shared__ float xs[DIM];
    __shared__ float lg[NEXP];
    const int t = blockIdx.x;
    const int tid = threadIdx.x;
    const int warp = tid >> 5, lane = tid & 31;

    const float4* xg = (const float4*)(x + (size_t)t * DIM);
    for (int i = tid; i < DIM / 4; i += 256) ((float4*)xs)[i] = xg[i];
    __syncthreads();

    // fused: emit fp16 copy of this token row
    for (int i = tid; i < DIM / 4; i += 256) {
        const float4 v = ((const float4*)xs)[i];
        __half2 h0 = __floats2half2_rn(v.x, v.y);
        __half2 h1 = __floats2half2_rn(v.z, v.w);
        uint2 u;
        u.x = *(uint32_t*)&h0; u.y = *(uint32_t*)&h1;
        *(uint2*)&g_Xh[(size_t)t * (DIM / 2) + 2 * i] = u;
    }

    {
        const float4* w0 = (const float4*)(rw + (size_t)(warp * 2) * DIM);
        const float4* w1 = (const float4*)(rw + (size_t)(warp * 2 + 1) * DIM);
        float a0 = 0.f, a1 = 0.f;
        for (int i = lane; i < DIM / 4; i += 32) {
            const float4 xv = ((const float4*)xs)[i];
            const float4 va = w0[i];
            const float4 vb = w1[i];
            a0 += xv.x * va.x + xv.y * va.y + xv.z * va.z + xv.w * va.w;
            a1 += xv.x * vb.x + xv.y * vb.y + xv.z * vb.z + xv.w * vb.w;
        }
        #pragma unroll
        for (int o = 16; o > 0; o >>= 1) {
            a0 += __shfl_xor_sync(0xffffffffu, a0, o);
            a1 += __shfl_xor_sync(0xffffffffu, a1, o);
        }
        if (lane == 0) { lg[warp * 2] = a0; lg[warp * 2 + 1] = a1; }
    }
    __syncthreads();
    if (write_logits && tid < NEXP)
        logits_out[(size_t)t * NEXP + tid] = lg[tid];
    if (tid == 0) {
        int i0 = 0;
        #pragma unroll
        for (int i = 1; i < NEXP; i++)
            if (lg[i] > lg[i0]) i0 = i;
        int i1 = (i0 == 0) ? 1 : 0;
        #pragma unroll
        for (int i = 0; i < NEXP; i++) {
            if (i == i0) continue;
            if (lg[i] > lg[i1]) i1 = i;
        }
        const float e1 = __expf(lg[i1] - lg[i0]);
        const float s = 1.0f + e1;
        g_tok_e[2 * t + 0] = i0; g_tok_w[2 * t + 0] = 1.0f / s;
        g_tok_e[2 * t + 1] = i1; g_tok_w[2 * t + 1] = e1 / s;
    }
}

// ---------------- compaction: smem-staged (kills the 82us serial global-latency loop) ----------------
__global__ void route_build_kernel() {
    __shared__ unsigned char s_e[NSLOT];    // 8 KB
    __shared__ float         s_wv[NSLOT];   // 32 KB
    __shared__ int s_cnt[NEXP];
    __shared__ int s_off[NEXP + 1];
    const int tid = threadIdx.x;            // 512 threads
    if (tid < NEXP) s_cnt[tid] = 0;
    __syncthreads();
    for (int i = tid; i < NSLOT; i += 512) {   // one coalesced pass; histogram inline
        const int ev = g_tok_e[i] & (NEXP - 1);
        s_e[i]  = (unsigned char)ev;
        s_wv[i] = g_tok_w[i];
        atomicAdd(&s_cnt[ev], 1);              // order-independent -> deterministic
    }
    __syncthreads();
    if (tid == 0) {
        int off = 0;
        #pragma unroll
        for (int e = 0; e < NEXP; e++) { s_off[e] = off; g_off[e] = off; off += s_cnt[e]; }
        s_off[NEXP] = off; g_off[NEXP] = off;
    }
    __syncthreads();
    const int warp = tid >> 5, lane = tid & 31;    // 16 warps, one per expert
    int base = s_off[warp];
    for (int i0 = 0; i0 < NSLOT; i0 += 32) {
        const int i = i0 + lane;
        const bool m = ((int)s_e[i] == warp);
        const unsigned mask = __ballot_sync(0xffffffffu, m);
        if (m) {
            const int pos = base + __popc(mask & ((1u << lane) - 1u));
            if (pos < NSLOT) {
                g_perm[pos] = i >> 1;
                g_wt[pos]   = s_wv[i];
            }
        }
        base += __popc(mask);
    }
}

// ================= fused gate+up fp16 GEMM (R12-proven mainloop) =================
// Tile M=128 x N=64 for BOTH gate and up. K=2048, chunk 32, 3-stage cp.async.
// Stage 20480 B: A 0..10240 | Bg 10240..15360 | Bu 15360..20480 (80 B row stride).
#define GU_SMEM (3 * 20480)
__global__ __launch_bounds__(256, 2)
void gu_kernel() {
    constexpr int NC = DIM / 32;
    extern __shared__ char smem[];
    __shared__ int   s_rows[128];
    __shared__ float s_w[128];

    const int tid = threadIdx.x;
    const int lane = tid & 31, wid = tid >> 5;
    const int wm = wid >> 1, wn = wid & 1;

    const int e  = blockIdx.y / MTILES;
    const int mt = blockIdx.y % MTILES;
    int segBeg = g_off[e], segEnd = g_off[e + 1];
    if (segBeg < 0) segBeg = 0;
    if (segEnd > NSLOT) segEnd = NSLOT;
    const int m0 = segBeg + mt * 128;
    if (m0 >= segEnd) return;
    const int mrem = segEnd - m0;
    const int n0 = blockIdx.x * 64;

    if (tid < 128) {
        const int idx = m0 + tid;
        int r = -1; float w = 0.f;
        if (idx < segEnd) {
            r = g_perm[idx];
            if (r < 0) r = 0;
            if (r >= T_TOK) r = T_TOK - 1;
            w = g_wt[idx];
        }
        s_rows[tid] = r; s_w[tid] = w;
    }
    __syncthreads();

    const uint32_t sb = smem_u32(smem);
    const int arow = tid >> 1, acg = tid & 1;

    auto ISSUE = [&](int c) {
        const uint32_t st = sb + (uint32_t)(c % 3) * 20480u;
        const int k0 = c * 32;
        {
            const int r = s_rows[arow];
            const uint32_t sz = (r >= 0) ? 16u : 0u;
            const size_t ao = (((size_t)(r < 0 ? 0 : r) * DIM + k0) >> 1) + (size_t)acg * 8;
            const uint32_t da = st + (uint32_t)(arow * 80 + acg * 32);
            const uint64_t sa = __cvta_generic_to_global((const void*)(g_Xh + ao));
            CP16(da,      sa,      sz);
            CP16(da + 16, sa + 16, sz);
        }
        {
            const int gu = arow >> 6;
            const int row = arow & 63;
            const size_t bo = (size_t)gu * (WSZ / 2)
                            + ((((size_t)e * FDIM + n0 + row) * DIM + k0) >> 1) + (size_t)acg * 8;
            const uint32_t db = st + 10240u + (uint32_t)(gu * 5120 + row * 80 + acg * 32);
            const uint64_t sb2 = __cvta_generic_to_global((const void*)(g_Wh + bo));
            CP16(db,      sb2,      16u);
            CP16(db + 16, sb2 + 16, 16u);
        }
        CP_COMMIT();
    };

    float acc[2][2][4][4];
    #pragma unroll
    for (int a = 0; a < 2; a++)
        #pragma unroll
        for (int b = 0; b < 2; b++)
            #pragma unroll
            for (int cN = 0; cN < 4; cN++)
                #pragma unroll
                for (int d = 0; d < 4; d++) acc[a][b][cN][d] = 0.f;

    const int lr = lane & 15, lh = lane >> 4;

    ISSUE(0); ISSUE(1);
    for (int c = 0; c < NC; c++) {
        if (c + 1 < NC) { CP_WAIT1(); } else { CP_WAIT0(); }
        __syncthreads();
        const uint32_t st = sb + (uint32_t)(c % 3) * 20480u;
        #pragma unroll
        for (int ks = 0; ks < 2; ks++) {
            uint32_t ah[2][4], bh[2][2][4];
            #pragma unroll
            for (int mi = 0; mi < 2; mi++)
                ldm4(ah[mi], st + (uint32_t)((wm * 32 + mi * 16 + lr) * 80 + ks * 32 + lh * 16));
            #pragma unroll
            for (int gu = 0; gu < 2; gu++)
                #pragma unroll
                for (int ni = 0; ni < 2; ni++)
                    ldm4(bh[gu][ni], st + 10240u + (uint32_t)(gu * 5120
                        + (wn * 32 + ni * 16 + lr) * 80 + ks * 32 + lh * 16));
            #pragma unroll
            for (int gu = 0; gu < 2; gu++)
                #pragma unroll
                for (int mi = 0; mi < 2; mi++)
                    #pragma unroll
                    for (int ni = 0; ni < 2; ni++)
                        #pragma unroll
                        for (int j = 0; j < 2; j++)
                            mma16816(acc[gu][mi][ni * 2 + j], ah[mi], bh[gu][ni][j], bh[gu][ni][j + 2]);
        }
        if (c + 2 < NC) ISSUE(c + 2);
        __syncthreads();
    }

    // ---- epilogue: h = wt * silu(g) * u -> fp16 -> g_Hh ----
    const int t4 = lane >> 2, l3 = lane & 3;
    #pragma unroll
    for (int mi = 0; mi < 2; mi++) {
        #pragma unroll
        for (int half = 0; half < 2; half++) {
            const int row = wm * 32 + mi * 16 + t4 + half * 8;
            if (row < mrem) {
                const float wt = s_w[row];
                const size_t base = (size_t)(m0 + row) * (FDIM / 2) + (size_t)((n0 + wn * 32) >> 1) + l3;
                #pragma unroll
                for (int nj = 0; nj < 4; nj++) {
                    const float gx = acc[0][mi][nj][half * 2 + 0];
                    const float gy = acc[0][mi][nj][half * 2 + 1];
                    const float ux = acc[1][mi][nj][half * 2 + 0];
                    const float uy = acc[1][mi][nj][half * 2 + 1];
                    const float hx = wt * ux * (gx / (1.f + __expf(-gx)));
                    const float hy = wt * uy * (gy / (1.f + __expf(-gy)));
                    __half2 hh = __floats2half2_rn(hx, hy);
                    g_Hh[base + nj * 4] = *(uint32_t*)&hh;
                }
            }
        }
    }
}

// ================= down fp16 GEMM (R12-proven mainloop, scatter-add epilogue) =================
#define DN_SMEM (3 * 20480)
__global__ __launch_bounds__(256, 2)
void dn_kernel(float* __restrict__ out) {
    constexpr int NC = FDIM / 32;
    extern __shared__ char smem[];

    const int tid = threadIdx.x;
    const int lane = tid & 31, wid = tid >> 5;
    const int wm = wid >> 2, wn = wid & 3;

    const int e  = blockIdx.y / MTILES;
    const int mt = blockIdx.y % MTILES;
    int segBeg = g_off[e], segEnd = g_off[e + 1];
    if (segBeg < 0) segBeg = 0;
    if (segEnd > NSLOT) segEnd = NSLOT;
    const int m0 = segBeg + mt * 128;
    if (m0 >= segEnd) return;
    const int mrem = segEnd - m0;
    const int n0 = blockIdx.x * 128;

    const uint32_t sb = smem_u32(smem);
    const int arow = tid >> 1, acg = tid & 1;

    auto ISSUE = [&](int c) {
        const uint32_t st = sb + (uint32_t)(c % 3) * 20480u;
        const int k0 = c * 32;
        {
            const uint32_t sz = (arow < mrem) ? 16u : 0u;
            const int r = m0 + ((arow < mrem) ? arow : 0);
            const size_t ao = (((size_t)r * FDIM + k0) >> 1) + (size_t)acg * 8;
            const uint32_t da = st + (uint32_t)(arow * 80 + acg * 32);
            const uint64_t sa = __cvta_generic_to_global((const void*)(g_Hh + ao));
            CP16(da,      sa,      sz);
            CP16(da + 16, sa + 16, sz);
        }
        {
            const size_t bo = WSZ + ((((size_t)e * DIM + n0 + arow) * FDIM + k0) >> 1) + (size_t)acg * 8;
            const uint32_t db = st + 10240u + (uint32_t)(arow * 80 + acg * 32);
            const uint64_t sb2 = __cvta_generic_to_global((const void*)(g_Wh + bo));
            CP16(db,      sb2,      16u);
            CP16(db + 16, sb2 + 16, 16u);
        }
        CP_COMMIT();
    };

    float acc[4][4][4];
    #pragma unroll
    for (int i = 0; i < 4; i++)
        #pragma unroll
        for (int j = 0; j < 4; j++)
            #pragma unroll
            for (int k = 0; k < 4; k++) acc[i][j][k] = 0.f;

    const int lr = lane & 15, lh = lane >> 4;
    const uint32_t aoffw = (uint32_t)((wm * 64 + lr) * 80 + lh * 16);
    const uint32_t boffw = (uint32_t)(10240 + (wn * 32 + lr) * 80 + lh * 16);

    ISSUE(0); ISSUE(1);
    for (int c = 0; c < NC; c++) {
        if (c + 1 < NC) { CP_WAIT1(); } else { CP_WAIT0(); }
        __syncthreads();
        const uint32_t st = sb + (uint32_t)(c % 3) * 20480u;
        #pragma unroll
        for (int ks = 0; ks < 2; ks++) {
            uint32_t ah[4][4], bh[2][4];
            #pragma unroll
            for (int mi = 0; mi < 4; mi++)
                ldm4(ah[mi], st + aoffw + mi * 16 * 80 + ks * 32);
            #pragma unroll
            for (int ni = 0; ni < 2; ni++)
                ldm4(bh[ni], st + boffw + ni * 16 * 80 + ks * 32);
            #pragma unroll
            for (int mi = 0; mi < 4; mi++)
                #pragma unroll
                for (int ni = 0; ni < 2; ni++)
                    #pragma unroll
                    for (int j = 0; j < 2; j++)
                        mma16816(acc[mi][ni * 2 + j], ah[mi], bh[ni][j], bh[ni][j + 2]);
        }
        if (c + 2 < NC) ISSUE(c + 2);
        __syncthreads();
    }

    const int t4 = lane >> 2, t2 = (lane & 3) * 2;
    #pragma unroll
    for (int mi = 0; mi < 4; mi++) {
        #pragma unroll
        for (int half = 0; half < 2; half++) {
            const int row = wm * 64 + mi * 16 + t4 + half * 8;
            if (row < mrem) {
                int tok = g_perm[m0 + row];
                if (tok < 0) tok = 0;
                if (tok >= T_TOK) tok = T_TOK - 1;
                float* orow = out + (size_t)tok * DIM + n0 + wn * 32;
                #pragma unroll
                for (int nj = 0; nj < 4; nj++) {
                    atomicAdd(orow + nj * 8 + t2,     acc[mi][nj][half * 2 + 0]);
                    atomicAdd(orow + nj * 8 + t2 + 1, acc[mi][nj][half * 2 + 1]);
                }
            }
        }
    }
}

// ---------------- launch ----------------
extern "C" void kernel_launch(void* const* d_in, const int* in_sizes, int n_in,
                              void* d_out, int out_size) {
    long long smax = -1;
    for (int i = 0; i < n_in; i++)
        if ((long long)in_sizes[i] > smax) smax = in_sizes[i];
    const float* w3[3] = {0, 0, 0};
    int wpos[3] = {-1, -1, -1};
    int nw = 0, ih = -1, irt = -1;
    for (int i = 0; i < n_in; i++)
        if ((long long)in_sizes[i] == smax && nw < 3) { w3[nw] = (const float*)d_in[i]; wpos[nw] = i; nw++; }
    long long best_h = -1;
    for (int i = 0; i < n_in; i++) {
        if (i == wpos[0] || i == wpos[1] || i == wpos[2]) continue;
        if ((long long)in_sizes[i] > best_h) { best_h = in_sizes[i]; ih = i; }
    }
    long long best_r = (long long)1 << 62;
    for (int i = 0; i < n_in; i++) {
        if (i == wpos[0] || i == wpos[1] || i == wpos[2] || i == ih) continue;
        if ((long long)in_sizes[i] < best_r) { best_r = in_sizes[i]; irt = i; }
    }
    const float* x  = (ih  >= 0) ? (const float*)d_in[ih]  : (const float*)d_in[0];
    const float* rw = (irt >= 0) ? (const float*)d_in[irt] : (const float*)d_in[1];
    const float *gw, *uw, *dw;
    if (nw == 3) {
        if (ih == 2) { dw = w3[0]; gw = w3[1]; uw = w3[2]; }
        else         { gw = w3[0]; uw = w3[1]; dw = w3[2]; }
    } else {
        x  = (const float*)d_in[0]; rw = (const float*)d_in[1];
        gw = (const float*)d_in[2]; uw = (const float*)d_in[3]; dw = (const float*)d_in[4];
    }
    float* out = (float*)d_out;

    const int need = T_TOK * DIM + T_TOK * NEXP;
    const int write_logits = (out_size >= need) ? 1 : 0;
    float* logits = out + (size_t)T_TOK * DIM;

    cudaFuncSetAttribute(gu_kernel, cudaFuncAttributeMaxDynamicSharedMemorySize, GU_SMEM);
    cudaFuncSetAttribute(dn_kernel, cudaFuncAttributeMaxDynamicSharedMemorySize, DN_SMEM);

    zero_out_kernel<<<(T_TOK * DIM / 4 + 255) / 256, 256>>>(out);
    conv_all_kernel<<<dim3(4096, 3), 256>>>((const float4*)gw, (const float4*)uw, (const float4*)dw);
    router_kernel<<<T_TOK, 256>>>(x, rw, logits, write_logits);
    route_build_kernel<<<1, 512>>>();

    gu_kernel<<<dim3(FDIM / 64, NEXP * MTILES), 256, GU_SMEM>>>();
    dn_kernel<<<dim3(DIM / 128, NEXP * MTILES), 256, DN_SMEM>>>(out);
}

// round 15
// speedup vs baseline: 1.1560x; 1.0565x over previous
#include <cuda_runtime.h>
#include <cuda_fp16.h>
#include <math.h>
#include <stdint.h>

#define T_TOK 4096
#define DIM   2048
#define NEXP  16
#define FDIM  768
#define NSLOT (T_TOK * 2)
#define MTILES 64
#define WSZ ((size_t)NEXP * FDIM * DIM)

// ---------------- device scratch; NEVER passed as kernel args (ATS host-shadow hazard) ----------------
__device__ __align__(16) int      g_cnt[NEXP];
__device__ __align__(16) int      g_pos[NEXP];
__device__ __align__(16) int      g_off[NEXP + 1];
__device__ __align__(16) int      g_tok_e[NSLOT];
__device__ __align__(16) float    g_tok_w[NSLOT];
__device__ __align__(16) int      g_perm[NSLOT];
__device__ __align__(16) float    g_wt[NSLOT];
__device__ __align__(16) uint32_t g_Wh[3 * WSZ / 2];              // fp16x2: [gate|up|down]
__device__ __align__(16) uint32_t g_Xh[(size_t)T_TOK * DIM / 2];  // x fp16
__device__ __align__(16) uint32_t g_Hh[(size_t)NSLOT * FDIM / 2]; // h fp16

// ---------------- helpers ----------------
__device__ __forceinline__ uint32_t smem_u32(const void* p) {
    uint32_t a;
    asm("{ .reg .u64 t; cvta.to.shared.u64 t, %1; cvt.u32.u64 %0, t; }" : "=r"(a) : "l"(p));
    return a;
}
#define CP16(dst, src, sz) \
    asm volatile("cp.async.cg.shared.global [%0], [%1], 16, %2;" \
        :: "r"(dst), "l"(src), "r"(sz) : "memory")
#define CP_COMMIT() asm volatile("cp.async.commit_group;" ::: "memory")
#define CP_WAIT1()  asm volatile("cp.async.wait_group 1;" ::: "memory")
#define CP_WAIT0()  asm volatile("cp.async.wait_group 0;" ::: "memory")

__device__ __forceinline__ void ldm4(uint32_t* r, uint32_t addr) {
    asm volatile("ldmatrix.sync.aligned.m8n8.x4.shared.b16 {%0,%1,%2,%3}, [%4];"
        : "=r"(r[0]), "=r"(r[1]), "=r"(r[2]), "=r"(r[3]) : "r"(addr));
}
__device__ __forceinline__ void mma16816(float* d, const uint32_t* a, uint32_t b0, uint32_t b1) {
    asm volatile(
        "mma.sync.aligned.m16n8k16.row.col.f32.f16.f16.f32 "
        "{%0,%1,%2,%3}, {%4,%5,%6,%7}, {%8,%9}, {%0,%1,%2,%3};"
        : "+f"(d[0]), "+f"(d[1]), "+f"(d[2]), "+f"(d[3])
        : "r"(a[0]), "r"(a[1]), "r"(a[2]), "r"(a[3]), "r"(b0), "r"(b1));
}

// ---------------- init counters ----------------
__global__ void init_cnt_kernel() {
    if (threadIdx.x < NEXP) g_cnt[threadIdx.x] = 0;
}

// ---------------- all-weights fp32 -> fp16 in ONE launch (grid.y = slice) ----------------
__global__ void conv_all_kernel(const float4* __restrict__ gw,
                                const float4* __restrict__ uw,
                                const float4* __restrict__ dw) {
    const int slice = blockIdx.y;
    const float4* src = (slice == 0) ? gw : (slice == 1) ? uw : dw;
    const size_t base = (size_t)slice * (WSZ / 2);
    const size_t n4 = WSZ / 4;
    for (size_t i = (size_t)blockIdx.x * blockDim.x + threadIdx.x; i < n4;
         i += (size_t)gridDim.x * blockDim.x) {
        const float4 v = src[i];
        __half2 h0 = __floats2half2_rn(v.x, v.y);
        __half2 h1 = __floats2half2_rn(v.z, v.w);
        uint2 u;
        u.x = *(uint32_t*)&h0; u.y = *(uint32_t*)&h1;
        *(uint2*)&g_Wh[base + 2 * i] = u;
    }
}

// ---------------- router + fused x->fp16 + fused out-row zeroing + histogram ----------------
__global__ __launch_bounds__(256)
void router_kernel(const float* __restrict__ x,
                   const float* __restrict__ rw,
                   float* __restrict__ out,
                   float* __restrict__ logits_out,
                   int write_logits) {
    __shared__ float xs[DIM];
    __shared__ float lg[NEXP];
    const int t = blockIdx.x;
    const int tid = threadIdx.x;
    const int warp = tid >> 5, lane = tid & 31;

    const float4* xg = (const float4*)(x + (size_t)t * DIM);
    float4* og = (float4*)(out + (size_t)t * DIM);
    for (int i = tid; i < DIM / 4; i += 256) {
        ((float4*)xs)[i] = xg[i];
        og[i] = make_float4(0.f, 0.f, 0.f, 0.f);   // fused zero of this token's out row
    }
    __syncthreads();

    // fused: emit fp16 copy of this token row
    for (int i = tid; i < DIM / 4; i += 256) {
        const float4 v = ((const float4*)xs)[i];
        __half2 h0 = __floats2half2_rn(v.x, v.y);
        __half2 h1 = __floats2half2_rn(v.z, v.w);
        uint2 u;
        u.x = *(uint32_t*)&h0; u.y = *(uint32_t*)&h1;
        *(uint2*)&g_Xh[(size_t)t * (DIM / 2) + 2 * i] = u;
    }

    {
        const float4* w0 = (const float4*)(rw + (size_t)(warp * 2) * DIM);
        const float4* w1 = (const float4*)(rw + (size_t)(warp * 2 + 1) * DIM);
        float a0 = 0.f, a1 = 0.f;
        for (int i = lane; i < DIM / 4; i += 32) {
            const float4 xv = ((const float4*)xs)[i];
            const float4 va = w0[i];
            const float4 vb = w1[i];
            a0 += xv.x * va.x + xv.y * va.y + xv.z * va.z + xv.w * va.w;
            a1 += xv.x * vb.x + xv.y * vb.y + xv.z * vb.z + xv.w * vb.w;
        }
        #pragma unroll
        for (int o = 16; o > 0; o >>= 1) {
            a0 += __shfl_xor_sync(0xffffffffu, a0, o);
            a1 += __shfl_xor_sync(0xffffffffu, a1, o);
        }
        if (lane == 0) { lg[warp * 2] = a0; lg[warp * 2 + 1] = a1; }
    }
    __syncthreads();
    if (write_logits && tid < NEXP)
        logits_out[(size_t)t * NEXP + tid] = lg[tid];
    if (tid == 0) {
        int i0 = 0;
        #pragma unroll
        for (int i = 1; i < NEXP; i++)
            if (lg[i] > lg[i0]) i0 = i;
        int i1 = (i0 == 0) ? 1 : 0;
        #pragma unroll
        for (int i = 0; i < NEXP; i++) {
            if (i == i0) continue;
            if (lg[i] > lg[i1]) i1 = i;
        }
        const float e1 = __expf(lg[i1] - lg[i0]);
        const float s = 1.0f + e1;
        g_tok_e[2 * t + 0] = i0; g_tok_w[2 * t + 0] = 1.0f / s;
        g_tok_e[2 * t + 1] = i1; g_tok_w[2 * t + 1] = e1 / s;
        atomicAdd(&g_cnt[i0], 1);
        atomicAdd(&g_cnt[i1], 1);
    }
}

// ---------------- offsets (tiny) ----------------
__global__ void offs_kernel() {
    if (threadIdx.x == 0) {
        int off = 0;
        #pragma unroll
        for (int e = 0; e < NEXP; e++) { g_off[e] = off; off += g_cnt[e]; }
        g_off[NEXP] = off;
    }
    if (threadIdx.x < NEXP) g_pos[threadIdx.x] = 0;
}

// ---------------- parallel scatter: order-free (output invariant by commutativity) ----------------
__global__ void scatter_kernel() {
    const int i = blockIdx.x * blockDim.x + threadIdx.x;
    if (i >= NSLOT) return;
    const int ev = g_tok_e[i] & (NEXP - 1);
    const int pos = g_off[ev] + atomicAdd(&g_pos[ev], 1);
    if (pos < NSLOT) {
        g_perm[pos] = i >> 1;
        g_wt[pos]   = g_tok_w[i];
    }
}

// ================= fused gate+up fp16 GEMM (R12/R14-proven mainloop) =================
#define GU_SMEM (3 * 20480)
__global__ __launch_bounds__(256, 2)
void gu_kernel() {
    constexpr int NC = DIM / 32;
    extern __shared__ char smem[];
    __shared__ int   s_rows[128];
    __shared__ float s_w[128];

    const int tid = threadIdx.x;
    const int lane = tid & 31, wid = tid >> 5;
    const int wm = wid >> 1, wn = wid & 1;

    const int e  = blockIdx.y / MTILES;
    const int mt = blockIdx.y % MTILES;
    int segBeg = g_off[e], segEnd = g_off[e + 1];
    if (segBeg < 0) segBeg = 0;
    if (segEnd > NSLOT) segEnd = NSLOT;
    const int m0 = segBeg + mt * 128;
    if (m0 >= segEnd) return;
    const int mrem = segEnd - m0;
    const int n0 = blockIdx.x * 64;

    if (tid < 128) {
        const int idx = m0 + tid;
        int r = -1; float w = 0.f;
        if (idx < segEnd) {
            r = g_perm[idx];
            if (r < 0) r = 0;
            if (r >= T_TOK) r = T_TOK - 1;
            w = g_wt[idx];
        }
        s_rows[tid] = r; s_w[tid] = w;
    }
    __syncthreads();

    const uint32_t sb = smem_u32(smem);
    const int arow = tid >> 1, acg = tid & 1;

    auto ISSUE = [&](int c) {
        const uint32_t st = sb + (uint32_t)(c % 3) * 20480u;
        const int k0 = c * 32;
        {
            const int r = s_rows[arow];
            const uint32_t sz = (r >= 0) ? 16u : 0u;
            const size_t ao = (((size_t)(r < 0 ? 0 : r) * DIM + k0) >> 1) + (size_t)acg * 8;
            const uint32_t da = st + (uint32_t)(arow * 80 + acg * 32);
            const uint64_t sa = __cvta_generic_to_global((const void*)(g_Xh + ao));
            CP16(da,      sa,      sz);
            CP16(da + 16, sa + 16, sz);
        }
        {
            const int gu = arow >> 6;
            const int row = arow & 63;
            const size_t bo = (size_t)gu * (WSZ / 2)
                            + ((((size_t)e * FDIM + n0 + row) * DIM + k0) >> 1) + (size_t)acg * 8;
            const uint32_t db = st + 10240u + (uint32_t)(gu * 5120 + row * 80 + acg * 32);
            const uint64_t sb2 = __cvta_generic_to_global((const void*)(g_Wh + bo));
            CP16(db,      sb2,      16u);
            CP16(db + 16, sb2 + 16, 16u);
        }
        CP_COMMIT();
    };

    float acc[2][2][4][4];
    #pragma unroll
    for (int a = 0; a < 2; a++)
        #pragma unroll
        for (int b = 0; b < 2; b++)
            #pragma unroll
            for (int cN = 0; cN < 4; cN++)
                #pragma unroll
                for (int d = 0; d < 4; d++) acc[a][b][cN][d] = 0.f;

    const int lr = lane & 15, lh = lane >> 4;

    ISSUE(0); ISSUE(1);
    for (int c = 0; c < NC; c++) {
        if (c + 1 < NC) { CP_WAIT1(); } else { CP_WAIT0(); }
        __syncthreads();
        const uint32_t st = sb + (uint32_t)(c % 3) * 20480u;
        #pragma unroll
        for (int ks = 0; ks < 2; ks++) {
            uint32_t ah[2][4], bh[2][2][4];
            #pragma unroll
            for (int mi = 0; mi < 2; mi++)
                ldm4(ah[mi], st + (uint32_t)((wm * 32 + mi * 16 + lr) * 80 + ks * 32 + lh * 16));
            #pragma unroll
            for (int gu = 0; gu < 2; gu++)
                #pragma unroll
                for (int ni = 0; ni < 2; ni++)
                    ldm4(bh[gu][ni], st + 10240u + (uint32_t)(gu * 5120
                        + (wn * 32 + ni * 16 + lr) * 80 + ks * 32 + lh * 16));
            #pragma unroll
            for (int gu = 0; gu < 2; gu++)
                #pragma unroll
                for (int mi = 0; mi < 2; mi++)
                    #pragma unroll
                    for (int ni = 0; ni < 2; ni++)
                        #pragma unroll
                        for (int j = 0; j < 2; j++)
                            mma16816(acc[gu][mi][ni * 2 + j], ah[mi], bh[gu][ni][j], bh[gu][ni][j + 2]);
        }
        if (c + 2 < NC) ISSUE(c + 2);
        __syncthreads();
    }

    const int t4 = lane >> 2, l3 = lane & 3;
    #pragma unroll
    for (int mi = 0; mi < 2; mi++) {
        #pragma unroll
        for (int half = 0; half < 2; half++) {
            const int row = wm * 32 + mi * 16 + t4 + half * 8;
            if (row < mrem) {
                const float wt = s_w[row];
                const size_t base = (size_t)(m0 + row) * (FDIM / 2) + (size_t)((n0 + wn * 32) >> 1) + l3;
                #pragma unroll
                for (int nj = 0; nj < 4; nj++) {
                    const float gx = acc[0][mi][nj][half * 2 + 0];
                    const float gy = acc[0][mi][nj][half * 2 + 1];
                    const float ux = acc[1][mi][nj][half * 2 + 0];
                    const float uy = acc[1][mi][nj][half * 2 + 1];
                    const float hx = wt * ux * (gx / (1.f + __expf(-gx)));
                    const float hy = wt * uy * (gy / (1.f + __expf(-gy)));
                    __half2 hh = __floats2half2_rn(hx, hy);
                    g_Hh[base + nj * 4] = *(uint32_t*)&hh;
                }
            }
        }
    }
}

// ================= down fp16 GEMM (proven mainloop, scatter-add epilogue) =================
#define DN_SMEM (3 * 20480)
__global__ __launch_bounds__(256, 2)
void dn_kernel(float* __restrict__ out) {
    constexpr int NC = FDIM / 32;
    extern __shared__ char smem[];

    const int tid = threadIdx.x;
    const int lane = tid & 31, wid = tid >> 5;
    const int wm = wid >> 2, wn = wid & 3;

    const int e  = blockIdx.y / MTILES;
    const int mt = blockIdx.y % MTILES;
    int segBeg = g_off[e], segEnd = g_off[e + 1];
    if (segBeg < 0) segBeg = 0;
    if (segEnd > NSLOT) segEnd = NSLOT;
    const int m0 = segBeg + mt * 128;
    if (m0 >= segEnd) return;
    const int mrem = segEnd - m0;
    const int n0 = blockIdx.x * 128;

    const uint32_t sb = smem_u32(smem);
    const int arow = tid >> 1, acg = tid & 1;

    auto ISSUE = [&](int c) {
        const uint32_t st = sb + (uint32_t)(c % 3) * 20480u;
        const int k0 = c * 32;
        {
            const uint32_t sz = (arow < mrem) ? 16u : 0u;
            const int r = m0 + ((arow < mrem) ? arow : 0);
            const size_t ao = (((size_t)r * FDIM + k0) >> 1) + (size_t)acg * 8;
            const uint32_t da = st + (uint32_t)(arow * 80 + acg * 32);
            const uint64_t sa = __cvta_generic_to_global((const void*)(g_Hh + ao));
            CP16(da,      sa,      sz);
            CP16(da + 16, sa + 16, sz);
        }
        {
            const size_t bo = WSZ + ((((size_t)e * DIM + n0 + arow) * FDIM + k0) >> 1) + (size_t)acg * 8;
            const uint32_t db = st + 10240u + (uint32_t)(arow * 80 + acg * 32);
            const uint64_t sb2 = __cvta_generic_to_global((const void*)(g_Wh + bo));
            CP16(db,      sb2,      16u);
            CP16(db + 16, sb2 + 16, 16u);
        }
        CP_COMMIT();
    };

    float acc[4][4][4];
    #pragma unroll
    for (int i = 0; i < 4; i++)
        #pragma unroll
        for (int j = 0; j < 4; j++)
            #pragma unroll
            for (int k = 0; k < 4; k++) acc[i][j][k] = 0.f;

    const int lr = lane & 15, lh = lane >> 4;
    const uint32_t aoffw = (uint32_t)((wm * 64 + lr) * 80 + lh * 16);
    const uint32_t boffw = (uint32_t)(10240 + (wn * 32 + lr) * 80 + lh * 16);

    ISSUE(0); ISSUE(1);
    for (int c = 0; c < NC; c++) {
        if (c + 1 < NC) { CP_WAIT1(); } else { CP_WAIT0(); }
        __syncthreads();
        const uint32_t st = sb + (uint32_t)(c % 3) * 20480u;
        #pragma unroll
        for (int ks = 0; ks < 2; ks++) {
            uint32_t ah[4][4], bh[2][4];
            #pragma unroll
            for (int mi = 0; mi < 4; mi++)
                ldm4(ah[mi], st + aoffw + mi * 16 * 80 + ks * 32);
            #pragma unroll
            for (int ni = 0; ni < 2; ni++)
                ldm4(bh[ni], st + boffw + ni * 16 * 80 + ks * 32);
            #pragma unroll
            for (int mi = 0; mi < 4; mi++)
                #pragma unroll
                for (int ni = 0; ni < 2; ni++)
                    #pragma unroll
                    for (int j = 0; j < 2; j++)
                        mma16816(acc[mi][ni * 2 + j], ah[mi], bh[ni][j], bh[ni][j + 2]);
        }
        if (c + 2 < NC) ISSUE(c + 2);
        __syncthreads();
    }

    const int t4 = lane >> 2, t2 = (lane & 3) * 2;
    #pragma unroll
    for (int mi = 0; mi < 4; mi++) {
        #pragma unroll
        for (int half = 0; half < 2; half++) {
            const int row = wm * 64 + mi * 16 + t4 + half * 8;
            if (row < mrem) {
                int tok = g_perm[m0 + row];
                if (tok < 0) tok = 0;
                if (tok >= T_TOK) tok = T_TOK - 1;
                float* orow = out + (size_t)tok * DIM + n0 + wn * 32;
                #pragma unroll
                for (int nj = 0; nj < 4; nj++) {
                    atomicAdd(orow + nj * 8 + t2,     acc[mi][nj][half * 2 + 0]);
                    atomicAdd(orow + nj * 8 + t2 + 1, acc[mi][nj][half * 2 + 1]);
                }
            }
        }
    }
}

// ---------------- launch ----------------
extern "C" void kernel_launch(void* const* d_in, const int* in_sizes, int n_in,
                              void* d_out, int out_size) {
    long long smax = -1;
    for (int i = 0; i < n_in; i++)
        if ((long long)in_sizes[i] > smax) smax = in_sizes[i];
    const float* w3[3] = {0, 0, 0};
    int wpos[3] = {-1, -1, -1};
    int nw = 0, ih = -1, irt = -1;
    for (int i = 0; i < n_in; i++)
        if ((long long)in_sizes[i] == smax && nw < 3) { w3[nw] = (const float*)d_in[i]; wpos[nw] = i; nw++; }
    long long best_h = -1;
    for (int i = 0; i < n_in; i++) {
        if (i == wpos[0] || i == wpos[1] || i == wpos[2]) continue;
        if ((long long)in_sizes[i] > best_h) { best_h = in_sizes[i]; ih = i; }
    }
    long long best_r = (long long)1 << 62;
    for (int i = 0; i < n_in; i++) {
        if (i == wpos[0] || i == wpos[1] || i == wpos[2] || i == ih) continue;
        if ((long long)in_sizes[i] < best_r) { best_r = in_sizes[i]; irt = i; }
    }
    const float* x  = (ih  >= 0) ? (const float*)d_in[ih]  : (const float*)d_in[0];
    const float* rw = (irt >= 0) ? (const float*)d_in[irt] : (const float*)d_in[1];
    const float *gw, *uw, *dw;
    if (nw == 3) {
        if (ih == 2) { dw = w3[0]; gw = w3[1]; uw = w3[2]; }
        else         { gw = w3[0]; uw = w3[1]; dw = w3[2]; }
    } else {
        x  = (const float*)d_in[0]; rw = (const float*)d_in[1];
        gw = (const float*)d_in[2]; uw = (const float*)d_in[3]; dw = (const float*)d_in[4];
    }
    float* out = (float*)d_out;

    const int need = T_TOK * DIM + T_TOK * NEXP;
    const int write_logits = (out_size >= need) ? 1 : 0;
    float* logits = out + (size_t)T_TOK * DIM;

    cudaFuncSetAttribute(gu_kernel, cudaFuncAttributeMaxDynamicSharedMemorySize, GU_SMEM);
    cudaFuncSetAttribute(dn_kernel, cudaFuncAttributeMaxDynamicSharedMemorySize, DN_SMEM);

    // fork a side stream so weight conversion overlaps the router chain
    cudaStream_t s1;
    cudaEvent_t ev_fork, ev_conv;
    cudaStreamCreateWithFlags(&s1, cudaStreamNonBlocking);
    cudaEventCreateWithFlags(&ev_fork, cudaEventDisableTiming);
    cudaEventCreateWithFlags(&ev_conv, cudaEventDisableTiming);

    cudaEventRecord(ev_fork, 0);
    cudaStreamWaitEvent(s1, ev_fork, 0);
    conv_all_kernel<<<dim3(4096, 3), 256, 0, s1>>>((const float4*)gw, (const float4*)uw, (const float4*)dw);
    cudaEventRecord(ev_conv, s1);

    init_cnt_kernel<<<1, 32>>>();
    router_kernel<<<T_TOK, 256>>>(x, rw, out, logits, write_logits);
    offs_kernel<<<1, 32>>>();
    scatter_kernel<<<NSLOT / 256, 256>>>();

    cudaStreamWaitEvent(0, ev_conv, 0);
    gu_kernel<<<dim3(FDIM / 64, NEXP * MTILES), 256, GU_SMEM>>>();
    dn_kernel<<<dim3(DIM / 128, NEXP * MTILES), 256, DN_SMEM>>>(out);
}

// round 16
// speedup vs baseline: 1.1875x; 1.0273x over previous
#include <cuda_runtime.h>
#include <cuda_fp16.h>
#include <math.h>
#include <stdint.h>

#define T_TOK 4096
#define DIM   2048
#define NEXP  16
#define FDIM  768
#define NSLOT (T_TOK * 2)
#define CAP   2048                  // per-expert slot capacity (mean 512; >60 sigma margin)
#define MTILES (CAP / 128)          // 16
#define WSZ ((size_t)NEXP * FDIM * DIM)

// ---------------- device scratch; NEVER passed as kernel args (ATS host-shadow hazard) ----------------
__device__ __align__(16) int      g_cnt[NEXP];
__device__ __align__(16) int      g_perm[NEXP * CAP];             // 2-D: expert-major slots
__device__ __align__(16) float    g_wt[NEXP * CAP];
__device__ __align__(16) uint32_t g_Wh[3 * WSZ / 2];              // fp16x2: [gate|up|down]
__device__ __align__(16) uint32_t g_Xh[(size_t)T_TOK * DIM / 2];  // x fp16
__device__ __align__(16) uint32_t g_Hh[(size_t)NEXP * CAP * FDIM / 2]; // h fp16 (expert-major)

// ---------------- helpers ----------------
__device__ __forceinline__ uint32_t smem_u32(const void* p) {
    uint32_t a;
    asm("{ .reg .u64 t; cvta.to.shared.u64 t, %1; cvt.u32.u64 %0, t; }" : "=r"(a) : "l"(p));
    return a;
}
#define CP16(dst, src, sz) \
    asm volatile("cp.async.cg.shared.global [%0], [%1], 16, %2;" \
        :: "r"(dst), "l"(src), "r"(sz) : "memory")
#define CP_COMMIT() asm volatile("cp.async.commit_group;" ::: "memory")
#define CP_WAIT1()  asm volatile("cp.async.wait_group 1;" ::: "memory")
#define CP_WAIT0()  asm volatile("cp.async.wait_group 0;" ::: "memory")

__device__ __forceinline__ void ldm4(uint32_t* r, uint32_t addr) {
    asm volatile("ldmatrix.sync.aligned.m8n8.x4.shared.b16 {%0,%1,%2,%3}, [%4];"
        : "=r"(r[0]), "=r"(r[1]), "=r"(r[2]), "=r"(r[3]) : "r"(addr));
}
__device__ __forceinline__ void mma16816(float* d, const uint32_t* a, uint32_t b0, uint32_t b1) {
    asm volatile(
        "mma.sync.aligned.m16n8k16.row.col.f32.f16.f16.f32 "
        "{%0,%1,%2,%3}, {%4,%5,%6,%7}, {%8,%9}, {%0,%1,%2,%3};"
        : "+f"(d[0]), "+f"(d[1]), "+f"(d[2]), "+f"(d[3])
        : "r"(a[0]), "r"(a[1]), "r"(a[2]), "r"(a[3]), "r"(b0), "r"(b1));
}

// ---------------- init counters ----------------
__global__ void init_cnt_kernel() {
    if (threadIdx.x < NEXP) g_cnt[threadIdx.x] = 0;
}

// ---------------- all-weights fp32 -> fp16 in ONE launch (grid.y = slice) ----------------
__global__ void conv_all_kernel(const float4* __restrict__ gw,
                                const float4* __restrict__ uw,
                                const float4* __restrict__ dw) {
    const int slice = blockIdx.y;
    const float4* src = (slice == 0) ? gw : (slice == 1) ? uw : dw;
    const size_t base = (size_t)slice * (WSZ / 2);
    const size_t n4 = WSZ / 4;
    for (size_t i = (size_t)blockIdx.x * blockDim.x + threadIdx.x; i < n4;
         i += (size_t)gridDim.x * blockDim.x) {
        const float4 v = src[i];
        __half2 h0 = __floats2half2_rn(v.x, v.y);
        __half2 h1 = __floats2half2_rn(v.z, v.w);
        uint2 u;
        u.x = *(uint32_t*)&h0; u.y = *(uint32_t*)&h1;
        *(uint2*)&g_Wh[base + 2 * i] = u;
    }
}

// ---------------- router + fused x->fp16 + fused out-row zeroing + direct 2-D scatter ----------------
__global__ __launch_bounds__(256)
void router_kernel(const float* __restrict__ x,
                   const float* __restrict__ rw,
                   float* __restrict__ out,
                   float* __restrict__ logits_out,
                   int write_logits) {
    __shared__ float xs[DIM];
    __shared__ float lg[NEXP];
    const int t = blockIdx.x;
    const int tid = threadIdx.x;
    const int warp = tid >> 5, lane = tid & 31;

    const float4* xg = (const float4*)(x + (size_t)t * DIM);
    float4* og = (float4*)(out + (size_t)t * DIM);
    for (int i = tid; i < DIM / 4; i += 256) {
        ((float4*)xs)[i] = xg[i];
        og[i] = make_float4(0.f, 0.f, 0.f, 0.f);   // fused zero of this token's out row
    }
    __syncthreads();

    // fused: emit fp16 copy of this token row
    for (int i = tid; i < DIM / 4; i += 256) {
        const float4 v = ((const float4*)xs)[i];
        __half2 h0 = __floats2half2_rn(v.x, v.y);
        __half2 h1 = __floats2half2_rn(v.z, v.w);
        uint2 u;
        u.x = *(uint32_t*)&h0; u.y = *(uint32_t*)&h1;
        *(uint2*)&g_Xh[(size_t)t * (DIM / 2) + 2 * i] = u;
    }

    {
        const float4* w0 = (const float4*)(rw + (size_t)(warp * 2) * DIM);
        const float4* w1 = (const float4*)(rw + (size_t)(warp * 2 + 1) * DIM);
        float a0 = 0.f, a1 = 0.f;
        for (int i = lane; i < DIM / 4; i += 32) {
            const float4 xv = ((const float4*)xs)[i];
            const float4 va = w0[i];
            const float4 vb = w1[i];
            a0 += xv.x * va.x + xv.y * va.y + xv.z * va.z + xv.w * va.w;
            a1 += xv.x * vb.x + xv.y * vb.y + xv.z * vb.z + xv.w * vb.w;
        }
        #pragma unroll
        for (int o = 16; o > 0; o >>= 1) {
            a0 += __shfl_xor_sync(0xffffffffu, a0, o);
            a1 += __shfl_xor_sync(0xffffffffu, a1, o);
        }
        if (lane == 0) { lg[warp * 2] = a0; lg[warp * 2 + 1] = a1; }
    }
    __syncthreads();
    if (write_logits && tid < NEXP)
        logits_out[(size_t)t * NEXP + tid] = lg[tid];
    if (tid == 0) {
        int i0 = 0;
        #pragma unroll
        for (int i = 1; i < NEXP; i++)
            if (lg[i] > lg[i0]) i0 = i;
        int i1 = (i0 == 0) ? 1 : 0;
        #pragma unroll
        for (int i = 0; i < NEXP; i++) {
            if (i == i0) continue;
            if (lg[i] > lg[i1]) i1 = i;
        }
        const float e1 = __expf(lg[i1] - lg[i0]);
        const float s = 1.0f + e1;
        // direct 2-D scatter: order within expert is irrelevant (2 commutative adds per out elem)
        const int p0 = atomicAdd(&g_cnt[i0], 1);
        if (p0 < CAP) { g_perm[i0 * CAP + p0] = t; g_wt[i0 * CAP + p0] = 1.0f / s; }
        const int p1 = atomicAdd(&g_cnt[i1], 1);
        if (p1 < CAP) { g_perm[i1 * CAP + p1] = t; g_wt[i1 * CAP + p1] = e1 / s; }
    }
}

// ================= fused gate+up fp16 GEMM (proven mainloop; expert-major slots) =================
#define GU_SMEM (3 * 20480)
__global__ __launch_bounds__(256, 2)
void gu_kernel() {
    constexpr int NC = DIM / 32;
    extern __shared__ char smem[];
    __shared__ int   s_rows[128];
    __shared__ float s_w[128];

    const int tid = threadIdx.x;
    const int lane = tid & 31, wid = tid >> 5;
    const int wm = wid >> 1, wn = wid & 1;

    const int e  = blockIdx.y / MTILES;
    const int mt = blockIdx.y % MTILES;
    int cnt = g_cnt[e];
    if (cnt > CAP) cnt = CAP;
    const int m0 = e * CAP + mt * 128;
    const int segEnd = e * CAP + cnt;
    if (m0 >= segEnd) return;
    const int mrem = segEnd - m0;
    const int n0 = blockIdx.x * 64;

    if (tid < 128) {
        const int idx = m0 + tid;
        int r = -1; float w = 0.f;
        if (idx < segEnd) {
            r = g_perm[idx];
            if (r < 0) r = 0;
            if (r >= T_TOK) r = T_TOK - 1;
            w = g_wt[idx];
        }
        s_rows[tid] = r; s_w[tid] = w;
    }
    __syncthreads();

    const uint32_t sb = smem_u32(smem);
    const int arow = tid >> 1, acg = tid & 1;

    auto ISSUE = [&](int c) {
        const uint32_t st = sb + (uint32_t)(c % 3) * 20480u;
        const int k0 = c * 32;
        {
            const int r = s_rows[arow];
            const uint32_t sz = (r >= 0) ? 16u : 0u;
            const size_t ao = (((size_t)(r < 0 ? 0 : r) * DIM + k0) >> 1) + (size_t)acg * 8;
            const uint32_t da = st + (uint32_t)(arow * 80 + acg * 32);
            const uint64_t sa = __cvta_generic_to_global((const void*)(g_Xh + ao));
            CP16(da,      sa,      sz);
            CP16(da + 16, sa + 16, sz);
        }
        {
            const int gu = arow >> 6;
            const int row = arow & 63;
            const size_t bo = (size_t)gu * (WSZ / 2)
                            + ((((size_t)e * FDIM + n0 + row) * DIM + k0) >> 1) + (size_t)acg * 8;
            const uint32_t db = st + 10240u + (uint32_t)(gu * 5120 + row * 80 + acg * 32);
            const uint64_t sb2 = __cvta_generic_to_global((const void*)(g_Wh + bo));
            CP16(db,      sb2,      16u);
            CP16(db + 16, sb2 + 16, 16u);
        }
        CP_COMMIT();
    };

    float acc[2][2][4][4];
    #pragma unroll
    for (int a = 0; a < 2; a++)
        #pragma unroll
        for (int b = 0; b < 2; b++)
            #pragma unroll
            for (int cN = 0; cN < 4; cN++)
                #pragma unroll
                for (int d = 0; d < 4; d++) acc[a][b][cN][d] = 0.f;

    const int lr = lane & 15, lh = lane >> 4;

    ISSUE(0); ISSUE(1);
    for (int c = 0; c < NC; c++) {
        if (c + 1 < NC) { CP_WAIT1(); } else { CP_WAIT0(); }
        __syncthreads();
        const uint32_t st = sb + (uint32_t)(c % 3) * 20480u;
        #pragma unroll
        for (int ks = 0; ks < 2; ks++) {
            uint32_t ah[2][4], bh[2][2][4];
            #pragma unroll
            for (int mi = 0; mi < 2; mi++)
                ldm4(ah[mi], st + (uint32_t)((wm * 32 + mi * 16 + lr) * 80 + ks * 32 + lh * 16));
            #pragma unroll
            for (int gu = 0; gu < 2; gu++)
                #pragma unroll
                for (int ni = 0; ni < 2; ni++)
                    ldm4(bh[gu][ni], st + 10240u + (uint32_t)(gu * 5120
                        + (wn * 32 + ni * 16 + lr) * 80 + ks * 32 + lh * 16));
            #pragma unroll
            for (int gu = 0; gu < 2; gu++)
                #pragma unroll
                for (int mi = 0; mi < 2; mi++)
                    #pragma unroll
                    for (int ni = 0; ni < 2; ni++)
                        #pragma unroll
                        for (int j = 0; j < 2; j++)
                            mma16816(acc[gu][mi][ni * 2 + j], ah[mi], bh[gu][ni][j], bh[gu][ni][j + 2]);
        }
        if (c + 2 < NC) ISSUE(c + 2);
        __syncthreads();
    }

    const int t4 = lane >> 2, l3 = lane & 3;
    #pragma unroll
    for (int mi = 0; mi < 2; mi++) {
        #pragma unroll
        for (int half = 0; half < 2; half++) {
            const int row = wm * 32 + mi * 16 + t4 + half * 8;
            if (row < mrem) {
                const float wt = s_w[row];
                const size_t base = (size_t)(m0 + row) * (FDIM / 2) + (size_t)((n0 + wn * 32) >> 1) + l3;
                #pragma unroll
                for (int nj = 0; nj < 4; nj++) {
                    const float gx = acc[0][mi][nj][half * 2 + 0];
                    const float gy = acc[0][mi][nj][half * 2 + 1];
                    const float ux = acc[1][mi][nj][half * 2 + 0];
                    const float uy = acc[1][mi][nj][half * 2 + 1];
                    const float hx = wt * ux * (gx / (1.f + __expf(-gx)));
                    const float hy = wt * uy * (gy / (1.f + __expf(-gy)));
                    __half2 hh = __floats2half2_rn(hx, hy);
                    g_Hh[base + nj * 4] = *(uint32_t*)&hh;
                }
            }
        }
    }
}

// ================= down fp16 GEMM (proven mainloop, scatter-add epilogue) =================
#define DN_SMEM (3 * 20480)
__global__ __launch_bounds__(256, 2)
void dn_kernel(float* __restrict__ out) {
    constexpr int NC = FDIM / 32;
    extern __shared__ char smem[];

    const int tid = threadIdx.x;
    const int lane = tid & 31, wid = tid >> 5;
    const int wm = wid >> 2, wn = wid & 3;

    const int e  = blockIdx.y / MTILES;
    const int mt = blockIdx.y % MTILES;
    int cnt = g_cnt[e];
    if (cnt > CAP) cnt = CAP;
    const int m0 = e * CAP + mt * 128;
    const int segEnd = e * CAP + cnt;
    if (m0 >= segEnd) return;
    const int mrem = segEnd - m0;
    const int n0 = blockIdx.x * 128;

    const uint32_t sb = smem_u32(smem);
    const int arow = tid >> 1, acg = tid & 1;

    auto ISSUE = [&](int c) {
        const uint32_t st = sb + (uint32_t)(c % 3) * 20480u;
        const int k0 = c * 32;
        {
            const uint32_t sz = (arow < mrem) ? 16u : 0u;
            const int r = m0 + ((arow < mrem) ? arow : 0);
            const size_t ao = (((size_t)r * FDIM + k0) >> 1) + (size_t)acg * 8;
            const uint32_t da = st + (uint32_t)(arow * 80 + acg * 32);
            const uint64_t sa = __cvta_generic_to_global((const void*)(g_Hh + ao));
            CP16(da,      sa,      sz);
            CP16(da + 16, sa + 16, sz);
        }
        {
            const size_t bo = WSZ + ((((size_t)e * DIM + n0 + arow) * FDIM + k0) >> 1) + (size_t)acg * 8;
            const uint32_t db = st + 10240u + (uint32_t)(arow * 80 + acg * 32);
            const uint64_t sb2 = __cvta_generic_to_global((const void*)(g_Wh + bo));
            CP16(db,      sb2,      16u);
            CP16(db + 16, sb2 + 16, 16u);
        }
        CP_COMMIT();
    };

    float acc[4][4][4];
    #pragma unroll
    for (int i = 0; i < 4; i++)
        #pragma unroll
        for (int j = 0; j < 4; j++)
            #pragma unroll
            for (int k = 0; k < 4; k++) acc[i][j][k] = 0.f;

    const int lr = lane & 15, lh = lane >> 4;
    const uint32_t aoffw = (uint32_t)((wm * 64 + lr) * 80 + lh * 16);
    const uint32_t boffw = (uint32_t)(10240 + (wn * 32 + lr) * 80 + lh * 16);

    ISSUE(0); ISSUE(1);
    for (int c = 0; c < NC; c++) {
        if (c + 1 < NC) { CP_WAIT1(); } else { CP_WAIT0(); }
        __syncthreads();
        const uint32_t st = sb + (uint32_t)(c % 3) * 20480u;
        #pragma unroll
        for (int ks = 0; ks < 2; ks++) {
            uint32_t ah[4][4], bh[2][4];
            #pragma unroll
            for (int mi = 0; mi < 4; mi++)
                ldm4(ah[mi], st + aoffw + mi * 16 * 80 + ks * 32);
            #pragma unroll
            for (int ni = 0; ni < 2; ni++)
                ldm4(bh[ni], st + boffw + ni * 16 * 80 + ks * 32);
            #pragma unroll
            for (int mi = 0; mi < 4; mi++)
                #pragma unroll
                for (int ni = 0; ni < 2; ni++)
                    #pragma unroll
                    for (int j = 0; j < 2; j++)
                        mma16816(acc[mi][ni * 2 + j], ah[mi], bh[ni][j], bh[ni][j + 2]);
        }
        if (c + 2 < NC) ISSUE(c + 2);
        __syncthreads();
    }

    const int t4 = lane >> 2, t2 = (lane & 3) * 2;
    #pragma unroll
    for (int mi = 0; mi < 4; mi++) {
        #pragma unroll
        for (int half = 0; half < 2; half++) {
            const int row = wm * 64 + mi * 16 + t4 + half * 8;
            if (row < mrem) {
                int tok = g_perm[m0 + row];
                if (tok < 0) tok = 0;
                if (tok >= T_TOK) tok = T_TOK - 1;
                float* orow = out + (size_t)tok * DIM + n0 + wn * 32;
                #pragma unroll
                for (int nj = 0; nj < 4; nj++) {
                    atomicAdd(orow + nj * 8 + t2,     acc[mi][nj][half * 2 + 0]);
                    atomicAdd(orow + nj * 8 + t2 + 1, acc[mi][nj][half * 2 + 1]);
                }
            }
        }
    }
}

// ---------------- launch ----------------
extern "C" void kernel_launch(void* const* d_in, const int* in_sizes, int n_in,
                              void* d_out, int out_size) {
    long long smax = -1;
    for (int i = 0; i < n_in; i++)
        if ((long long)in_sizes[i] > smax) smax = in_sizes[i];
    const float* w3[3] = {0, 0, 0};
    int wpos[3] = {-1, -1, -1};
    int nw = 0, ih = -1, irt = -1;
    for (int i = 0; i < n_in; i++)
        if ((long long)in_sizes[i] == smax && nw < 3) { w3[nw] = (const float*)d_in[i]; wpos[nw] = i; nw++; }
    long long best_h = -1;
    for (int i = 0; i < n_in; i++) {
        if (i == wpos[0] || i == wpos[1] || i == wpos[2]) continue;
        if ((long long)in_sizes[i] > best_h) { best_h = in_sizes[i]; ih = i; }
    }
    long long best_r = (long long)1 << 62;
    for (int i = 0; i < n_in; i++) {
        if (i == wpos[0] || i == wpos[1] || i == wpos[2] || i == ih) continue;
        if ((long long)in_sizes[i] < best_r) { best_r = in_sizes[i]; irt = i; }
    }
    const float* x  = (ih  >= 0) ? (const float*)d_in[ih]  : (const float*)d_in[0];
    const float* rw = (irt >= 0) ? (const float*)d_in[irt] : (const float*)d_in[1];
    const float *gw, *uw, *dw;
    if (nw == 3) {
        if (ih == 2) { dw = w3[0]; gw = w3[1]; uw = w3[2]; }
        else         { gw = w3[0]; uw = w3[1]; dw = w3[2]; }
    } else {
        x  = (const float*)d_in[0]; rw = (const float*)d_in[1];
        gw = (const float*)d_in[2]; uw = (const float*)d_in[3]; dw = (const float*)d_in[4];
    }
    float* out = (float*)d_out;

    const int need = T_TOK * DIM + T_TOK * NEXP;
    const int write_logits = (out_size >= need) ? 1 : 0;
    float* logits = out + (size_t)T_TOK * DIM;

    cudaFuncSetAttribute(gu_kernel, cudaFuncAttributeMaxDynamicSharedMemorySize, GU_SMEM);
    cudaFuncSetAttribute(dn_kernel, cudaFuncAttributeMaxDynamicSharedMemorySize, DN_SMEM);

    // fork a side stream so weight conversion overlaps the router chain
    cudaStream_t s1;
    cudaEvent_t ev_fork, ev_conv;
    cudaStreamCreateWithFlags(&s1, cudaStreamNonBlocking);
    cudaEventCreateWithFlags(&ev_fork, cudaEventDisableTiming);
    cudaEventCreateWithFlags(&ev_conv, cudaEventDisableTiming);

    cudaEventRecord(ev_fork, 0);
    cudaStreamWaitEvent(s1, ev_fork, 0);
    conv_all_kernel<<<dim3(8192, 3), 256, 0, s1>>>((const float4*)gw, (const float4*)uw, (const float4*)dw);
    cudaEventRecord(ev_conv, s1);

    init_cnt_kernel<<<1, 32>>>();
    router_kernel<<<T_TOK, 256>>>(x, rw, out, logits, write_logits);

    cudaStreamWaitEvent(0, ev_conv, 0);
    gu_kernel<<<dim3(FDIM / 64, NEXP * MTILES), 256, GU_SMEM>>>();
    dn_kernel<<<dim3(DIM / 128, NEXP * MTILES), 256, DN_SMEM>>>(out);
}

// round 17
// speedup vs baseline: 1.2102x; 1.0191x over previous
#include <cuda_runtime.h>
#include <cuda_fp16.h>
#include <math.h>
#include <stdint.h>

#define T_TOK 4096
#define DIM   2048
#define NEXP  16
#define FDIM  768
#define NSLOT (T_TOK * 2)
#define CAP   2048
#define MT64  (CAP / 64)            // 32 m-tiles per expert
#define WSZ ((size_t)NEXP * FDIM * DIM)

// ---------------- device scratch; NEVER passed as kernel args (ATS host-shadow hazard) ----------------
__device__ __align__(16) int      g_cnt[NEXP];
__device__ __align__(16) int      g_perm[NEXP * CAP];
__device__ __align__(16) float    g_wt[NEXP * CAP];
__device__ __align__(16) uint32_t g_Wh[3 * WSZ / 2];              // fp16x2: [gate|up|down]
__device__ __align__(16) uint32_t g_Xh[(size_t)T_TOK * DIM / 2];  // x fp16
__device__ __align__(16) uint32_t g_Hh[(size_t)NEXP * CAP * FDIM / 2]; // h fp16 (expert-major)

// ---------------- helpers ----------------
__device__ __forceinline__ uint32_t smem_u32(const void* p) {
    uint32_t a;
    asm("{ .reg .u64 t; cvta.to.shared.u64 t, %1; cvt.u32.u64 %0, t; }" : "=r"(a) : "l"(p));
    return a;
}
#define CP16(dst, src, sz) \
    asm volatile("cp.async.cg.shared.global [%0], [%1], 16, %2;" \
        :: "r"(dst), "l"(src), "r"(sz) : "memory")
#define CP_COMMIT() asm volatile("cp.async.commit_group;" ::: "memory")
#define CP_WAIT1()  asm volatile("cp.async.wait_group 1;" ::: "memory")
#define CP_WAIT0()  asm volatile("cp.async.wait_group 0;" ::: "memory")

__device__ __forceinline__ void ldm4(uint32_t* r, uint32_t addr) {
    asm volatile("ldmatrix.sync.aligned.m8n8.x4.shared.b16 {%0,%1,%2,%3}, [%4];"
        : "=r"(r[0]), "=r"(r[1]), "=r"(r[2]), "=r"(r[3]) : "r"(addr));
}
__device__ __forceinline__ void mma16816(float* d, const uint32_t* a, uint32_t b0, uint32_t b1) {
    asm volatile(
        "mma.sync.aligned.m16n8k16.row.col.f32.f16.f16.f32 "
        "{%0,%1,%2,%3}, {%4,%5,%6,%7}, {%8,%9}, {%0,%1,%2,%3};"
        : "+f"(d[0]), "+f"(d[1]), "+f"(d[2]), "+f"(d[3])
        : "r"(a[0]), "r"(a[1]), "r"(a[2]), "r"(a[3]), "r"(b0), "r"(b1));
}

// ---------------- init counters ----------------
__global__ void init_cnt_kernel() {
    if (threadIdx.x < NEXP) g_cnt[threadIdx.x] = 0;
}

// ---------------- all-weights fp32 -> fp16 in ONE launch (grid.y = slice) ----------------
__global__ void conv_all_kernel(const float4* __restrict__ gw,
                                const float4* __restrict__ uw,
                                const float4* __restrict__ dw) {
    const int slice = blockIdx.y;
    const float4* src = (slice == 0) ? gw : (slice == 1) ? uw : dw;
    const size_t base = (size_t)slice * (WSZ / 2);
    const size_t n4 = WSZ / 4;
    for (size_t i = (size_t)blockIdx.x * blockDim.x + threadIdx.x; i < n4;
         i += (size_t)gridDim.x * blockDim.x) {
        const float4 v = src[i];
        __half2 h0 = __floats2half2_rn(v.x, v.y);
        __half2 h1 = __floats2half2_rn(v.z, v.w);
        uint2 u;
        u.x = *(uint32_t*)&h0; u.y = *(uint32_t*)&h1;
        *(uint2*)&g_Wh[base + 2 * i] = u;
    }
}

// ---------------- router + fused x->fp16 + fused out-row zeroing + direct 2-D scatter ----------------
__global__ __launch_bounds__(256)
void router_kernel(const float* __restrict__ x,
                   const float* __restrict__ rw,
                   float* __restrict__ out,
                   float* __restrict__ logits_out,
                   int write_logits) {
    __shared__ float xs[DIM];
    __shared__ float lg[NEXP];
    const int t = blockIdx.x;
    const int tid = threadIdx.x;
    const int warp = tid >> 5, lane = tid & 31;

    const float4* xg = (const float4*)(x + (size_t)t * DIM);
    float4* og = (float4*)(out + (size_t)t * DIM);
    for (int i = tid; i < DIM / 4; i += 256) {
        ((float4*)xs)[i] = xg[i];
        og[i] = make_float4(0.f, 0.f, 0.f, 0.f);
    }
    __syncthreads();

    for (int i = tid; i < DIM / 4; i += 256) {
        const float4 v = ((const float4*)xs)[i];
        __half2 h0 = __floats2half2_rn(v.x, v.y);
        __half2 h1 = __floats2half2_rn(v.z, v.w);
        uint2 u;
        u.x = *(uint32_t*)&h0; u.y = *(uint32_t*)&h1;
        *(uint2*)&g_Xh[(size_t)t * (DIM / 2) + 2 * i] = u;
    }

    {
        const float4* w0 = (const float4*)(rw + (size_t)(warp * 2) * DIM);
        const float4* w1 = (const float4*)(rw + (size_t)(warp * 2 + 1) * DIM);
        float a0 = 0.f, a1 = 0.f;
        for (int i = lane; i < DIM / 4; i += 32) {
            const float4 xv = ((const float4*)xs)[i];
            const float4 va = w0[i];
            const float4 vb = w1[i];
            a0 += xv.x * va.x + xv.y * va.y + xv.z * va.z + xv.w * va.w;
            a1 += xv.x * vb.x + xv.y * vb.y + xv.z * vb.z + xv.w * vb.w;
        }
        #pragma unroll
        for (int o = 16; o > 0; o >>= 1) {
            a0 += __shfl_xor_sync(0xffffffffu, a0, o);
            a1 += __shfl_xor_sync(0xffffffffu, a1, o);
        }
        if (lane == 0) { lg[warp * 2] = a0; lg[warp * 2 + 1] = a1; }
    }
    __syncthreads();
    if (write_logits && tid < NEXP)
        logits_out[(size_t)t * NEXP + tid] = lg[tid];
    if (tid == 0) {
        int i0 = 0;
        #pragma unroll
        for (int i = 1; i < NEXP; i++)
            if (lg[i] > lg[i0]) i0 = i;
        int i1 = (i0 == 0) ? 1 : 0;
        #pragma unroll
        for (int i = 0; i < NEXP; i++) {
            if (i == i0) continue;
            if (lg[i] > lg[i1]) i1 = i;
        }
        const float e1 = __expf(lg[i1] - lg[i0]);
        const float s = 1.0f + e1;
        const int p0 = atomicAdd(&g_cnt[i0], 1);
        if (p0 < CAP) { g_perm[i0 * CAP + p0] = t; g_wt[i0 * CAP + p0] = 1.0f / s; }
        const int p1 = atomicAdd(&g_cnt[i1], 1);
        if (p1 < CAP) { g_perm[i1 * CAP + p1] = t; g_wt[i1 * CAP + p1] = e1 / s; }
    }
}

// ================= fused gate+up fp16 GEMM: M=64 tile, 3 CTAs/SM =================
// Stage 15360 B: A(64x80) 0..5120 | Bg 5120..10240 | Bu 10240..15360
#define GU_SMEM (3 * 15360)
__global__ __launch_bounds__(256, 3)
void gu_kernel() {
    constexpr int NC = DIM / 32;
    extern __shared__ char smem[];
    __shared__ int   s_rows[64];
    __shared__ float s_w[64];

    const int tid = threadIdx.x;
    const int lane = tid & 31, wid = tid >> 5;
    const int wm = wid >> 2, wn = wid & 3;      // 2m x 4n warps; warp tile 32m x 16n per matrix

    const int e  = blockIdx.y / MT64;
    const int mt = blockIdx.y % MT64;
    int cnt = g_cnt[e];
    if (cnt > CAP) cnt = CAP;
    const int m0 = e * CAP + mt * 64;
    const int segEnd = e * CAP + cnt;
    if (m0 >= segEnd) return;
    const int mrem = segEnd - m0;
    const int n0 = blockIdx.x * 64;

    if (tid < 64) {
        const int idx = m0 + tid;
        int r = -1; float w = 0.f;
        if (idx < segEnd) {
            r = g_perm[idx];
            if (r < 0) r = 0;
            if (r >= T_TOK) r = T_TOK - 1;
            w = g_wt[idx];
        }
        s_rows[tid] = r; s_w[tid] = w;
    }
    __syncthreads();

    const uint32_t sb = smem_u32(smem);
    const int ar = tid >> 2, aq = tid & 3;      // A: 64 rows x 4 16B-segs
    const int br = tid >> 1, bq = tid & 1;      // B: 128 rows (gate|up) x 2 32B-segs

    auto ISSUE = [&](int c) {
        const uint32_t st = sb + (uint32_t)(c % 3) * 15360u;
        const int k0 = c * 32;
        {   // A: gathered x fp16 (1 cp of 16B per thread)
            const int r = s_rows[ar];
            const uint32_t sz = (r >= 0) ? 16u : 0u;
            const size_t ao = (((size_t)(r < 0 ? 0 : r) * DIM + k0) >> 1) + (size_t)aq * 4;
            CP16(st + (uint32_t)(ar * 80 + aq * 16),
                 __cvta_generic_to_global((const void*)(g_Xh + ao)), sz);
        }
        {   // B: gate rows 0-63, up rows 64-127 (2 cps of 16B per thread)
            const int gu = br >> 6;
            const int row = br & 63;
            const size_t bo = (size_t)gu * (WSZ / 2)
                            + ((((size_t)e * FDIM + n0 + row) * DIM + k0) >> 1) + (size_t)bq * 8;
            const uint32_t db = st + 5120u + (uint32_t)(gu * 5120 + row * 80 + bq * 32);
            const uint64_t sb2 = __cvta_generic_to_global((const void*)(g_Wh + bo));
            CP16(db,      sb2,      16u);
            CP16(db + 16, sb2 + 16, 16u);
        }
        CP_COMMIT();
    };

    float acc[2][2][2][4];   // [gu][mi][nj][4]
    #pragma unroll
    for (int a = 0; a < 2; a++)
        #pragma unroll
        for (int b = 0; b < 2; b++)
            #pragma unroll
            for (int cN = 0; cN < 2; cN++)
                #pragma unroll
                for (int d = 0; d < 4; d++) acc[a][b][cN][d] = 0.f;

    const int lr = lane & 15, lh = lane >> 4;

    ISSUE(0); ISSUE(1);
    for (int c = 0; c < NC; c++) {
        if (c + 1 < NC) { CP_WAIT1(); } else { CP_WAIT0(); }
        __syncthreads();
        const uint32_t st = sb + (uint32_t)(c % 3) * 15360u;
        #pragma unroll
        for (int ks = 0; ks < 2; ks++) {
            uint32_t ah[2][4], bh[2][4];
            #pragma unroll
            for (int mi = 0; mi < 2; mi++)
                ldm4(ah[mi], st + (uint32_t)((wm * 32 + mi * 16 + lr) * 80 + ks * 32 + lh * 16));
            #pragma unroll
            for (int gu = 0; gu < 2; gu++)
                ldm4(bh[gu], st + 5120u + (uint32_t)(gu * 5120
                    + (wn * 16 + lr) * 80 + ks * 32 + lh * 16));
            #pragma unroll
            for (int gu = 0; gu < 2; gu++)
                #pragma unroll
                for (int mi = 0; mi < 2; mi++)
                    #pragma unroll
                    for (int j = 0; j < 2; j++)
                        mma16816(acc[gu][mi][j], ah[mi], bh[gu][j], bh[gu][j + 2]);
        }
        if (c + 2 < NC) ISSUE(c + 2);
        __syncthreads();
    }

    // ---- epilogue: h = wt * silu(g) * u -> fp16 -> g_Hh ----
    const int t4 = lane >> 2, l3 = lane & 3;
    #pragma unroll
    for (int mi = 0; mi < 2; mi++) {
        #pragma unroll
        for (int half = 0; half < 2; half++) {
            const int row = wm * 32 + mi * 16 + t4 + half * 8;
            if (row < mrem) {
                const float wt = s_w[row];
                const size_t base = (size_t)(m0 + row) * (FDIM / 2)
                                  + (size_t)((n0 + wn * 16) >> 1) + l3;
                #pragma unroll
                for (int nj = 0; nj < 2; nj++) {
                    const float gx = acc[0][mi][nj][half * 2 + 0];
                    const float gy = acc[0][mi][nj][half * 2 + 1];
                    const float ux = acc[1][mi][nj][half * 2 + 0];
                    const float uy = acc[1][mi][nj][half * 2 + 1];
                    const float hx = wt * ux * (gx / (1.f + __expf(-gx)));
                    const float hy = wt * uy * (gy / (1.f + __expf(-gy)));
                    __half2 hh = __floats2half2_rn(hx, hy);
                    g_Hh[base + nj * 4] = *(uint32_t*)&hh;
                }
            }
        }
    }
}

// ================= down fp16 GEMM: M=64 x N=128 tile, 3 CTAs/SM =================
// Stage 15360 B: A(64x80) 0..5120 | B(128x80) 5120..15360
#define DN_SMEM (3 * 15360)
__global__ __launch_bounds__(256, 3)
void dn_kernel(float* __restrict__ out) {
    constexpr int NC = FDIM / 32;
    extern __shared__ char smem[];

    const int tid = threadIdx.x;
    const int lane = tid & 31, wid = tid >> 5;
    const int wm = wid >> 2, wn = wid & 3;      // warp tile 32m x 32n

    const int e  = blockIdx.y / MT64;
    const int mt = blockIdx.y % MT64;
    int cnt = g_cnt[e];
    if (cnt > CAP) cnt = CAP;
    const int m0 = e * CAP + mt * 64;
    const int segEnd = e * CAP + cnt;
    if (m0 >= segEnd) return;
    const int mrem = segEnd - m0;
    const int n0 = blockIdx.x * 128;

    const uint32_t sb = smem_u32(smem);
    const int ar = tid >> 2, aq = tid & 3;
    const int br = tid >> 1, bq = tid & 1;

    auto ISSUE = [&](int c) {
        const uint32_t st = sb + (uint32_t)(c % 3) * 15360u;
        const int k0 = c * 32;
        {   // A: h fp16, slot-indexed
            const uint32_t sz = (ar < mrem) ? 16u : 0u;
            const int r = m0 + ((ar < mrem) ? ar : 0);
            const size_t ao = (((size_t)r * FDIM + k0) >> 1) + (size_t)aq * 4;
            CP16(st + (uint32_t)(ar * 80 + aq * 16),
                 __cvta_generic_to_global((const void*)(g_Hh + ao)), sz);
        }
        {   // B: down weights (slice 2)
            const size_t bo = WSZ + ((((size_t)e * DIM + n0 + br) * FDIM + k0) >> 1) + (size_t)bq * 8;
            const uint32_t db = st + 5120u + (uint32_t)(br * 80 + bq * 32);
            const uint64_t sb2 = __cvta_generic_to_global((const void*)(g_Wh + bo));
            CP16(db,      sb2,      16u);
            CP16(db + 16, sb2 + 16, 16u);
        }
        CP_COMMIT();
    };

    float acc[2][4][4];   // [mi][nj][4]
    #pragma unroll
    for (int i = 0; i < 2; i++)
        #pragma unroll
        for (int j = 0; j < 4; j++)
            #pragma unroll
            for (int k = 0; k < 4; k++) acc[i][j][k] = 0.f;

    const int lr = lane & 15, lh = lane >> 4;

    ISSUE(0); ISSUE(1);
    for (int c = 0; c < NC; c++) {
        if (c + 1 < NC) { CP_WAIT1(); } else { CP_WAIT0(); }
        __syncthreads();
        const uint32_t st = sb + (uint32_t)(c % 3) * 15360u;
        #pragma unroll
        for (int ks = 0; ks < 2; ks++) {
            uint32_t ah[2][4], bh[2][4];
            #pragma unroll
            for (int mi = 0; mi < 2; mi++)
                ldm4(ah[mi], st + (uint32_t)((wm * 32 + mi * 16 + lr) * 80 + ks * 32 + lh * 16));
            #pragma unroll
            for (int ni = 0; ni < 2; ni++)
                ldm4(bh[ni], st + 5120u + (uint32_t)((wn * 32 + ni * 16 + lr) * 80 + ks * 32 + lh * 16));
            #pragma unroll
            for (int mi = 0; mi < 2; mi++)
                #pragma unroll
                for (int ni = 0; ni < 2; ni++)
                    #pragma unroll
                    for (int j = 0; j < 2; j++)
                        mma16816(acc[mi][ni * 2 + j], ah[mi], bh[ni][j], bh[ni][j + 2]);
        }
        if (c + 2 < NC) ISSUE(c + 2);
        __syncthreads();
    }

    // ---- epilogue: scatter-add ----
    const int t4 = lane >> 2, t2 = (lane & 3) * 2;
    #pragma unroll
    for (int mi = 0; mi < 2; mi++) {
        #pragma unroll
        for (int half = 0; half < 2; half++) {
            const int row = wm * 32 + mi * 16 + t4 + half * 8;
            if (row < mrem) {
                int tok = g_perm[m0 + row];
                if (tok < 0) tok = 0;
                if (tok >= T_TOK) tok = T_TOK - 1;
                float* orow = out + (size_t)tok * DIM + n0 + wn * 32;
                #pragma unroll
                for (int nj = 0; nj < 4; nj++) {
                    atomicAdd(orow + nj * 8 + t2,     acc[mi][nj][half * 2 + 0]);
                    atomicAdd(orow + nj * 8 + t2 + 1, acc[mi][nj][half * 2 + 1]);
                }
            }
        }
    }
}

// ---------------- launch ----------------
extern "C" void kernel_launch(void* const* d_in, const int* in_sizes, int n_in,
                              void* d_out, int out_size) {
    long long smax = -1;
    for (int i = 0; i < n_in; i++)
        if ((long long)in_sizes[i] > smax) smax = in_sizes[i];
    const float* w3[3] = {0, 0, 0};
    int wpos[3] = {-1, -1, -1};
    int nw = 0, ih = -1, irt = -1;
    for (int i = 0; i < n_in; i++)
        if ((long long)in_sizes[i] == smax && nw < 3) { w3[nw] = (const float*)d_in[i]; wpos[nw] = i; nw++; }
    long long best_h = -1;
    for (int i = 0; i < n_in; i++) {
        if (i == wpos[0] || i == wpos[1] || i == wpos[2]) continue;
        if ((long long)in_sizes[i] > best_h) { best_h = in_sizes[i]; ih = i; }
    }
    long long best_r = (long long)1 << 62;
    for (int i = 0; i < n_in; i++) {
        if (i == wpos[0] || i == wpos[1] || i == wpos[2] || i == ih) continue;
        if ((long long)in_sizes[i] < best_r) { best_r = in_sizes[i]; irt = i; }
    }
    const float* x  = (ih  >= 0) ? (const float*)d_in[ih]  : (const float*)d_in[0];
    const float* rw = (irt >= 0) ? (const float*)d_in[irt] : (const float*)d_in[1];
    const float *gw, *uw, *dw;
    if (nw == 3) {
        if (ih == 2) { dw = w3[0]; gw = w3[1]; uw = w3[2]; }
        else         { gw = w3[0]; uw = w3[1]; dw = w3[2]; }
    } else {
        x  = (const float*)d_in[0]; rw = (const float*)d_in[1];
        gw = (const float*)d_in[2]; uw = (const float*)d_in[3]; dw = (const float*)d_in[4];
    }
    float* out = (float*)d_out;

    const int need = T_TOK * DIM + T_TOK * NEXP;
    const int write_logits = (out_size >= need) ? 1 : 0;
    float* logits = out + (size_t)T_TOK * DIM;

    cudaFuncSetAttribute(gu_kernel, cudaFuncAttributeMaxDynamicSharedMemorySize, GU_SMEM);
    cudaFuncSetAttribute(dn_kernel, cudaFuncAttributeMaxDynamicSharedMemorySize, DN_SMEM);

    // fork a side stream so weight conversion overlaps the router chain
    cudaStream_t s1;
    cudaEvent_t ev_fork, ev_conv;
    cudaStreamCreateWithFlags(&s1, cudaStreamNonBlocking);
    cudaEventCreateWithFlags(&ev_fork, cudaEventDisableTiming);
    cudaEventCreateWithFlags(&ev_conv, cudaEventDisableTiming);

    cudaEventRecord(ev_fork, 0);
    cudaStreamWaitEvent(s1, ev_fork, 0);
    conv_all_kernel<<<dim3(8192, 3), 256, 0, s1>>>((const float4*)gw, (const float4*)uw, (const float4*)dw);
    cudaEventRecord(ev_conv, s1);

    init_cnt_kernel<<<1, 32>>>();
    router_kernel<<<T_TOK, 256>>>(x, rw, out, logits, write_logits);

    cudaStreamWaitEvent(0, ev_conv, 0);
    gu_kernel<<<dim3(FDIM / 64, NEXP * MT64), 256, GU_SMEM>>>();
    dn_kernel<<<dim3(DIM / 128, NEXP * MT64), 256, DN_SMEM>>>(out);
}